// round 2
// baseline (speedup 1.0000x reference)
#include <cuda_runtime.h>
#include <math.h>

#define HIDDEN 256
#define TM 64
#define MPAD 260            // padded activation row stride (floats); 16B-aligned rows
#define NTHR 256
#define PIX_PER_BATCH (128*128)
#define TOTAL_PIX (16*PIX_PER_BATCH)
#define OUT_PIX (TOTAL_PIX*3)

// dynamic smem layout (floats):
//   bufA   [TM][MPAD]      = 16640
//   bufB   [TM][MPAD]      = 16640
//   Ws     [16][HIDDEN]    = 4096
//   coords [2][TM]         = 128
#define SMEM_FLOATS (TM*MPAD*2 + 16*HIDDEN + 2*TM)
#define SMEM_BYTES  (SMEM_FLOATS*4)

// One 256->256 dense layer with ReLU for a 64-pixel tile.
// in_s/out_s: [TM][MPAD] activation buffers. Ws: 16xHIDDEN staging tile.
// Thread (tx,ty): tx in [0,32) owns outputs n0=tx*8..+7; ty in [0,8) owns pixels m0=ty*8..+7.
__device__ __forceinline__ void dense256(
    const float* __restrict__ W, const float* __restrict__ bias,
    const float* in_s, float* out_s, float* Ws,
    int tid, int tx, int ty)
{
    float acc[8][8];
#pragma unroll
    for (int i = 0; i < 8; i++)
#pragma unroll
        for (int j = 0; j < 8; j++) acc[i][j] = 0.f;

    const int m0 = ty * 8, n0 = tx * 8;

    for (int k0 = 0; k0 < HIDDEN; k0 += 16) {
        __syncthreads();   // protect Ws from previous iter's readers (also post-producer barrier at k0=0)
        // stage W[k0:k0+16, :] -> Ws (4096 floats, 16/thread via float4)
        const float4* Wg = reinterpret_cast<const float4*>(W + k0 * HIDDEN);
        float4* Wsv = reinterpret_cast<float4*>(Ws);
#pragma unroll
        for (int i = 0; i < 4; i++) Wsv[tid + i * NTHR] = Wg[tid + i * NTHR];
        __syncthreads();

#pragma unroll
        for (int kk = 0; kk < 16; kk++) {
            float a[8];
#pragma unroll
            for (int i = 0; i < 8; i++) a[i] = in_s[(m0 + i) * MPAD + k0 + kk];  // warp-broadcast
            float4 w0 = *reinterpret_cast<const float4*>(&Ws[kk * HIDDEN + n0]);
            float4 w1 = *reinterpret_cast<const float4*>(&Ws[kk * HIDDEN + n0 + 4]);
            float w[8] = {w0.x, w0.y, w0.z, w0.w, w1.x, w1.y, w1.z, w1.w};
#pragma unroll
            for (int i = 0; i < 8; i++)
#pragma unroll
                for (int j = 0; j < 8; j++)
                    acc[i][j] = fmaf(a[i], w[j], acc[i][j]);
        }
    }

    // epilogue: bias + ReLU, store 8x8 tile (2x float4 per pixel row)
    float bb[8];
#pragma unroll
    for (int j = 0; j < 8; j++) bb[j] = bias[n0 + j];
#pragma unroll
    for (int i = 0; i < 8; i++) {
        float v[8];
#pragma unroll
        for (int j = 0; j < 8; j++) v[j] = fmaxf(acc[i][j] + bb[j], 0.f);
        *reinterpret_cast<float4*>(&out_s[(m0 + i) * MPAD + n0]) =
            make_float4(v[0], v[1], v[2], v[3]);
        *reinterpret_cast<float4*>(&out_s[(m0 + i) * MPAD + n0 + 4]) =
            make_float4(v[4], v[5], v[6], v[7]);
    }
}

__global__ void __launch_bounds__(NTHR, 1) inr_fused_kernel(
    const float* __restrict__ x,            // (B,H,W,2)
    const int*   __restrict__ sample_idx,   // (B,)
    const float* __restrict__ shiftv,       // (16,2) [dy,dx]
    const float* __restrict__ rotang,       // (16,1)
    const float* __restrict__ cscales,      // (16,3)
    const float* __restrict__ cshifts,      // (16,3)
    const float* __restrict__ W1, const float* __restrict__ b1,   // (2,256),(256)
    const float* __restrict__ W2, const float* __restrict__ b2,   // (256,256),(256)
    const float* __restrict__ W3, const float* __restrict__ b3,   // (256,256),(256)
    const float* __restrict__ W4, const float* __restrict__ b4,   // (256,3),(3)
    float* __restrict__ out)                // 786432 (+16 dx)(+16 dy)
{
    extern __shared__ float smem[];
    float* bufA   = smem;
    float* bufB   = bufA + TM * MPAD;
    float* Ws     = bufB + TM * MPAD;
    float* coords = Ws + 16 * HIDDEN;       // [2][TM]

    const int tid = threadIdx.x;
    const int tx = tid & 31, ty = tid >> 5;
    const int p0 = blockIdx.x * TM;         // blocks are batch-aligned (16384 px / batch)
    const int b  = p0 / PIX_PER_BATCH;

    const int   sidx = sample_idx[b];
    const float dyv  = shiftv[sidx * 2 + 0];
    const float dxv  = shiftv[sidx * 2 + 1];
    const float ang  = rotang[sidx];
    float sv, cv;
    sincosf(ang, &sv, &cv);

    // per-pixel rotated+shifted coords
    if (tid < TM) {
        float2 xv = reinterpret_cast<const float2*>(x)[p0 + tid];
        coords[tid]      = cv * xv.x - sv * xv.y + dxv;   // coord 0
        coords[TM + tid] = sv * xv.x + cv * xv.y + dyv;   // coord 1
    }
    __syncthreads();

    // layer 1: 2 -> 256, ReLU, into bufA
    {
        const int m0 = ty * 8, n0 = tx * 8;
        float wa[8], wb[8], bb[8];
#pragma unroll
        for (int j = 0; j < 8; j++) {
            wa[j] = W1[n0 + j];
            wb[j] = W1[HIDDEN + n0 + j];
            bb[j] = b1[n0 + j];
        }
#pragma unroll
        for (int i = 0; i < 8; i++) {
            float c0 = coords[m0 + i];
            float c1 = coords[TM + m0 + i];
            float v[8];
#pragma unroll
            for (int j = 0; j < 8; j++) {
                float t = fmaf(c1, wb[j], bb[j]);
                t = fmaf(c0, wa[j], t);
                v[j] = fmaxf(t, 0.f);
            }
            *reinterpret_cast<float4*>(&bufA[(m0 + i) * MPAD + n0]) =
                make_float4(v[0], v[1], v[2], v[3]);
            *reinterpret_cast<float4*>(&bufA[(m0 + i) * MPAD + n0 + 4]) =
                make_float4(v[4], v[5], v[6], v[7]);
        }
    }
    // dense256 opens with __syncthreads(), which orders the bufA writes above

    dense256(W2, b2, bufA, bufB, Ws, tid, tx, ty);   // layer 2: bufA -> bufB
    dense256(W3, b3, bufB, bufA, Ws, tid, tx, ty);   // layer 3: bufB -> bufA
    __syncthreads();

    // layer 4: 256 -> 3, plus per-sample color affine
    if (tid < TM * 3) {
        const int m = tid / 3, j = tid - 3 * m;
        const float* hrow = &bufA[m * MPAD];
        float s = 0.f;
#pragma unroll 8
        for (int k = 0; k < HIDDEN; k++)
            s = fmaf(hrow[k], W4[k * 3 + j], s);     // W4 is 3KB: L1-resident
        s += b4[j];
        if (sidx != 0)
            s = fmaf(s, cscales[sidx * 3 + j], cshifts[sidx * 3 + j]);
        out[(p0 + m) * 3 + j] = s;
    }

    // dx / dy passthrough outputs (one writer per batch)
    if ((blockIdx.x & 255) == 0 && tid == 0) {
        out[OUT_PIX + b]      = dxv;   // dx = shift[:,1]
        out[OUT_PIX + 16 + b] = dyv;   // dy = shift[:,0]
    }
}

extern "C" void kernel_launch(void* const* d_in, const int* in_sizes, int n_in,
                              void* d_out, int out_size)
{
    (void)in_sizes; (void)n_in; (void)out_size;
    const float* x      = (const float*)d_in[0];
    const int*   sidx   = (const int*)  d_in[1];
    const float* shiftv = (const float*)d_in[2];
    const float* rotang = (const float*)d_in[3];
    const float* cscal  = (const float*)d_in[4];
    const float* cshft  = (const float*)d_in[5];
    const float* W1 = (const float*)d_in[6];
    const float* b1 = (const float*)d_in[7];
    const float* W2 = (const float*)d_in[8];
    const float* b2 = (const float*)d_in[9];
    const float* W3 = (const float*)d_in[10];
    const float* b3 = (const float*)d_in[11];
    const float* W4 = (const float*)d_in[12];
    const float* b4 = (const float*)d_in[13];
    float* out = (float*)d_out;

    cudaFuncSetAttribute(inr_fused_kernel,
                         cudaFuncAttributeMaxDynamicSharedMemorySize, SMEM_BYTES);

    inr_fused_kernel<<<TOTAL_PIX / TM, NTHR, SMEM_BYTES>>>(
        x, sidx, shiftv, rotang, cscal, cshft,
        W1, b1, W2, b2, W3, b3, W4, b4, out);
}

// round 4
// speedup vs baseline: 2.4936x; 2.4936x over previous
#include <cuda_runtime.h>
#include <cuda_fp16.h>
#include <cstdint>
#include <math.h>

#define NTHR 256
#define NTILES 4096
#define OUT_PIX (16*128*128*3)

// ---- smem byte offsets ----
#define OFF_STAGE(s) ((s)*40960)     // 2 stages: Whi 20480 + Wlo 20480
#define W_LO_OFF 20480
#define OFF_AH  81920                // A hi: [64 m][256 k] fp16, 512B rows, XOR-swizzled 16B chunks
#define OFF_AL  147456               // A lo
#define OFF_W1A 212992
#define OFF_W1B 214016
#define OFF_B1  215040
#define OFF_B2  216064
#define OFF_B3  217088
#define OFF_W4  218112               // float[768]
#define OFF_PART 221184              // float[256*3]
#define OFF_MB  224256               // F0,F1,U0,U1
#define MB_F(s) (OFF_MB + (s)*8)
#define MB_U(s) (OFF_MB + 16 + (s)*8)
#define SMEM_ALLOC 224384

// Pre-split weight images: [layer][hi/lo][kchunk(8 x k32)][256 n x 80B rows]
// row stride 80B = 5*16B (odd multiple of 16 -> conflict-free ldmatrix, no XOR needed)
__device__ __align__(16) unsigned char g_W[2][2][8][20480];

// ---- helpers ----
__device__ __forceinline__ uint32_t smem_u32(const void* p) {
    uint32_t a;
    asm("{ .reg .u64 t; cvta.to.shared.u64 t, %1; cvt.u32.u64 %0, t; }" : "=r"(a) : "l"(p));
    return a;
}
#define MBAR_INIT(mbar, cnt) \
    asm volatile("mbarrier.init.shared.b64 [%0], %1;" :: "r"((uint32_t)(mbar)), "r"((uint32_t)(cnt)) : "memory")
#define MBAR_EXPECT_TX(mbar, tx) \
    asm volatile("mbarrier.arrive.expect_tx.shared.b64 _, [%0], %1;" :: "r"((uint32_t)(mbar)), "r"((uint32_t)(tx)) : "memory")
#define MBAR_ARRIVE(mbar) \
    asm volatile("mbarrier.arrive.shared.b64 _, [%0];" :: "r"((uint32_t)(mbar)) : "memory")

__device__ __forceinline__ void mbar_wait(uint32_t mbar, uint32_t parity) {
    uint32_t done;
    asm volatile("{\n\t.reg .pred p;\n\t"
                 "mbarrier.try_wait.parity.acquire.cta.shared::cta.b64 p, [%1], %2;\n\t"
                 "selp.b32 %0, 1, 0, p;\n\t}" : "=r"(done) : "r"(mbar), "r"(parity) : "memory");
    if (!done) {
        asm volatile("{\n\t.reg .pred P1;\n\t"
                     "W_%=:\n\t"
                     "mbarrier.try_wait.parity.acquire.cta.shared::cta.b64 P1, [%0], %1, 0x989680;\n\t"
                     "@P1 bra.uni D_%=;\n\t"
                     "bra.uni W_%=;\n\t"
                     "D_%=:\n\t}" :: "r"(mbar), "r"(parity) : "memory");
    }
}
__device__ __forceinline__ void bulk_ld(uint32_t dst, const void* src, uint32_t bytes, uint32_t mbar) {
    asm volatile("cp.async.bulk.shared::cluster.global.mbarrier::complete_tx::bytes [%0], [%1], %2, [%3];"
                 :: "r"(dst), "l"(src), "r"(bytes), "r"(mbar) : "memory");
}
#define LDSM4(r, addr) \
    asm volatile("ldmatrix.sync.aligned.m8n8.x4.shared.b16 {%0,%1,%2,%3}, [%4];" \
        : "=r"((r)[0]), "=r"((r)[1]), "=r"((r)[2]), "=r"((r)[3]) : "r"(addr))
#define MMA4(dd, a, b0_, b1_) \
    asm volatile("mma.sync.aligned.m16n8k16.row.col.f32.f16.f16.f32 " \
        "{%0,%1,%2,%3}, {%4,%5,%6,%7}, {%8,%9}, {%0,%1,%2,%3};" \
        : "+f"((dd)[0]), "+f"((dd)[1]), "+f"((dd)[2]), "+f"((dd)[3]) \
        : "r"((a)[0]), "r"((a)[1]), "r"((a)[2]), "r"((a)[3]), "r"(b0_), "r"(b1_))

// A smem address: [m][k] fp16, 512B rows, physical 16B chunk = (k/8) ^ (m&7)
__device__ __forceinline__ uint32_t a_addr(uint32_t base, int m, int k) {
    return base + (uint32_t)(m * 512) +
           (uint32_t)(((((k >> 3) ^ (m & 7))) << 4) + ((k & 7) << 1));
}
__device__ __forceinline__ void store_split(unsigned char* sm, int m, int n, float v0, float v1) {
    __half h0 = __float2half_rn(v0), h1 = __float2half_rn(v1);
    __half l0 = __float2half_rn(v0 - __half2float(h0));
    __half l1 = __float2half_rn(v1 - __half2float(h1));
    *(__half2*)(sm + a_addr(OFF_AH, m, n)) = __halves2half2(h0, h1);
    *(__half2*)(sm + a_addr(OFF_AL, m, n)) = __halves2half2(l0, l1);
}

// ---- prep: split W2/W3 into fp16 hi/lo [n][k] images, 80B rows ----
__global__ void prep_kernel(const float* __restrict__ W2, const float* __restrict__ W3) {
    int idx = blockIdx.x * blockDim.x + threadIdx.x;   // 0..131071
    int l = idx >> 16, r = idx & 65535;
    int k = r >> 8, n = r & 255;
    float w = (l ? W3 : W2)[k * 256 + n];
    __half h = __float2half_rn(w);
    __half lo = __float2half_rn(w - __half2float(h));
    int kc = k >> 5, kk = k & 31;
    *(__half*)&g_W[l][0][kc][n * 80 + kk * 2] = h;
    *(__half*)&g_W[l][1][kc][n * 80 + kk * 2] = lo;
}

__device__ __forceinline__ void issue_load(uint32_t smb, int g) {
    const int lc = g & 15;                    // 16 chunks per tile
    const int l = lc >> 3, kc = lc & 7, s = g & 1;
    const uint32_t mb = smb + MB_F(s);
    const uint32_t dst = smb + OFF_STAGE(s);
    MBAR_EXPECT_TX(mb, 40960);
    bulk_ld(dst,            &g_W[l][0][kc][0], 20480, mb);
    bulk_ld(dst + W_LO_OFF, &g_W[l][1][kc][0], 20480, mb);
}

// one 256->256 layer: 8 k-chunks of 32, 3-term split HMMA
__device__ __forceinline__ void run_layer(
    float (&d)[2][8][4], uint32_t smb, int m0, int n0,
    int lane, int tid, int& g, int total_chunks)
{
    const int aRow = (lane & 7) + ((lane >> 3) & 1) * 8;   // ldmatrix A row-in-tile
    const int aCs  = lane >> 4;                            // A chunk select (0/1)
    const int wRow = ((lane >> 4) & 1) * 8 + (lane & 7);   // ldmatrix B row (n)
    const int wCs  = (lane >> 3) & 1;                      // B chunk select

    const int mA0 = m0 + aRow, mA1 = m0 + 16 + aRow;
    const uint32_t aB0h = smb + OFF_AH + mA0 * 512, aB1h = smb + OFF_AH + mA1 * 512;
    const uint32_t aB0l = smb + OFF_AL + mA0 * 512, aB1l = smb + OFF_AL + mA1 * 512;
    const int ax0 = mA0 & 7, ax1 = mA1 & 7;

    for (int kc = 0; kc < 8; kc++) {
        const int s = g & 1;
        const uint32_t ph = (uint32_t)((g >> 1) & 1);
        mbar_wait(smb + MB_F(s), ph);
        const uint32_t stH = smb + OFF_STAGE(s);
        const uint32_t stL = stH + W_LO_OFF;
#pragma unroll
        for (int ks = 0; ks < 2; ks++) {
            const int cb = kc * 4 + ks * 2 + aCs;          // A 16B-chunk index
            uint32_t ah0[4], ah1[4], al0[4], al1[4];
            LDSM4(ah0, aB0h + (uint32_t)((cb ^ ax0) << 4));
            LDSM4(ah1, aB1h + (uint32_t)((cb ^ ax1) << 4));
            LDSM4(al0, aB0l + (uint32_t)((cb ^ ax0) << 4));
            LDSM4(al1, aB1l + (uint32_t)((cb ^ ax1) << 4));
            const uint32_t wko = (uint32_t)((ks * 2 + wCs) << 4);
#pragma unroll
            for (int np = 0; np < 4; np++) {
                const uint32_t wro = (uint32_t)((n0 + np * 16 + wRow) * 80) + wko;
                uint32_t wh[4], wl[4];
                LDSM4(wh, stH + wro);
                LDSM4(wl, stL + wro);
                MMA4(d[0][np*2],   ah0, wh[0], wh[1]);
                MMA4(d[1][np*2],   ah1, wh[0], wh[1]);
                MMA4(d[0][np*2],   al0, wh[0], wh[1]);
                MMA4(d[1][np*2],   al1, wh[0], wh[1]);
                MMA4(d[0][np*2],   ah0, wl[0], wl[1]);
                MMA4(d[1][np*2],   ah1, wl[0], wl[1]);
                MMA4(d[0][np*2+1], ah0, wh[2], wh[3]);
                MMA4(d[1][np*2+1], ah1, wh[2], wh[3]);
                MMA4(d[0][np*2+1], al0, wh[2], wh[3]);
                MMA4(d[1][np*2+1], al1, wh[2], wh[3]);
                MMA4(d[0][np*2+1], ah0, wl[2], wl[3]);
                MMA4(d[1][np*2+1], ah1, wl[2], wl[3]);
            }
        }
        MBAR_ARRIVE(smb + MB_U(s));                       // all 256 threads
        if (tid == 0 && g + 2 < total_chunks) {
            mbar_wait(smb + MB_U(s), ph);                  // stage fully consumed
            issue_load(smb, g + 2);
        }
        g++;
    }
}

__device__ __forceinline__ void epi_store(
    unsigned char* sm, float (&d)[2][8][4], const float* bias,
    int m0, int n0, int qm, int qn)
{
#pragma unroll
    for (int mt = 0; mt < 2; mt++) {
        const int mA = m0 + mt * 16 + qm;
#pragma unroll
        for (int nt = 0; nt < 8; nt++) {
            const int n = n0 + nt * 8 + qn;
            const float bb0 = bias[n], bb1 = bias[n + 1];
            store_split(sm, mA,     n, fmaxf(d[mt][nt][0] + bb0, 0.f), fmaxf(d[mt][nt][1] + bb1, 0.f));
            store_split(sm, mA + 8, n, fmaxf(d[mt][nt][2] + bb0, 0.f), fmaxf(d[mt][nt][3] + bb1, 0.f));
        }
    }
}

__global__ void __launch_bounds__(NTHR, 1) inr_hmma_kernel(
    const float* __restrict__ x, const int* __restrict__ sample_idx,
    const float* __restrict__ shiftv, const float* __restrict__ rotang,
    const float* __restrict__ cscal, const float* __restrict__ cshft,
    const float* __restrict__ W1, const float* __restrict__ b1,
    const float* __restrict__ b2, const float* __restrict__ b3,
    const float* __restrict__ W4, const float* __restrict__ b4,
    float* __restrict__ out)
{
    extern __shared__ __align__(128) unsigned char sm[];
    const uint32_t smb = smem_u32(sm);

    const int tid = threadIdx.x;
    const int lane = tid & 31, wid = tid >> 5;
    const int m0 = (wid & 1) * 32, n0 = (wid >> 1) * 64;    // warp tile 32x64
    const int qm = lane >> 2, qn = (lane & 3) * 2;

    float* w1a = (float*)(sm + OFF_W1A);
    float* w1b = (float*)(sm + OFF_W1B);
    float* b1v = (float*)(sm + OFF_B1);
    float* b2v = (float*)(sm + OFF_B2);
    float* b3v = (float*)(sm + OFF_B3);
    float* w4s = (float*)(sm + OFF_W4);
    float* part = (float*)(sm + OFF_PART);

    w1a[tid] = W1[tid]; w1b[tid] = W1[256 + tid];
    b1v[tid] = b1[tid]; b2v[tid] = b2[tid]; b3v[tid] = b3[tid];
    w4s[tid] = W4[tid]; w4s[tid + 256] = W4[tid + 256]; w4s[tid + 512] = W4[tid + 512];
    if (tid == 0) {
        MBAR_INIT(smb + MB_F(0), 1);   MBAR_INIT(smb + MB_F(1), 1);
        MBAR_INIT(smb + MB_U(0), NTHR); MBAR_INIT(smb + MB_U(1), NTHR);
    }
    __syncthreads();

    const int bid = blockIdx.x, grid = gridDim.x;
    const int ntiles = (NTILES - 1 - bid) / grid + 1;
    const int total_chunks = ntiles * 16;
    int g = 0;
    if (tid == 0) { issue_load(smb, 0); issue_load(smb, 1); }

    const float2* x2 = (const float2*)x;

    for (int t = bid; t < NTILES; t += grid) {
        const int b = t >> 8;                 // 256 tiles per batch
        const int p0 = t * 64;
        const int sidx = sample_idx[b];
        const float dyv = shiftv[sidx * 2], dxv = shiftv[sidx * 2 + 1];
        float sv, cvv;
        sincosf(rotang[sidx], &sv, &cvv);

        // ---- layer 1 (SIMT) -> A hi/lo smem ----
        {
            const int px = tid >> 2, q = tid & 3;
            float2 xv = x2[p0 + px];
            const float c0 = cvv * xv.x - sv * xv.y + dxv;
            const float c1 = sv * xv.x + cvv * xv.y + dyv;
#pragma unroll
            for (int i = 0; i < 32; i++) {
                const int n = q * 64 + i * 2;
                float h0 = fmaxf(fmaf(c0, w1a[n],     fmaf(c1, w1b[n],     b1v[n])),     0.f);
                float h1 = fmaxf(fmaf(c0, w1a[n + 1], fmaf(c1, w1b[n + 1], b1v[n + 1])), 0.f);
                store_split(sm, px, n, h0, h1);
            }
            if (tid == 255 && (t & 255) == 0) {
                out[OUT_PIX + b] = dxv;
                out[OUT_PIX + 16 + b] = dyv;
            }
        }
        __syncthreads();

        float d[2][8][4];
#pragma unroll
        for (int i = 0; i < 2; i++)
#pragma unroll
            for (int j = 0; j < 8; j++)
#pragma unroll
                for (int kq = 0; kq < 4; kq++) d[i][j][kq] = 0.f;
        run_layer(d, smb, m0, n0, lane, tid, g, total_chunks);   // layer 2
        __syncthreads();
        epi_store(sm, d, b2v, m0, n0, qm, qn);
        __syncthreads();

#pragma unroll
        for (int i = 0; i < 2; i++)
#pragma unroll
            for (int j = 0; j < 8; j++)
#pragma unroll
                for (int kq = 0; kq < 4; kq++) d[i][j][kq] = 0.f;
        run_layer(d, smb, m0, n0, lane, tid, g, total_chunks);   // layer 3
        __syncthreads();
        epi_store(sm, d, b3v, m0, n0, qm, qn);
        __syncthreads();

        // ---- layer 4: 4 threads per pixel, 64 k each ----
        {
            const int px = tid >> 2, q = tid & 3;
            float o0 = 0.f, o1 = 0.f, o2 = 0.f;
#pragma unroll 8
            for (int kk = 0; kk < 64; kk += 2) {
                const int k = q * 64 + kk;
                uint32_t ah = *(const uint32_t*)(sm + a_addr(OFF_AH, px, k));
                uint32_t al = *(const uint32_t*)(sm + a_addr(OFF_AL, px, k));
                __half2 h2 = *(__half2*)&ah, l2 = *(__half2*)&al;
                float v0 = __half2float(__low2half(h2))  + __half2float(__low2half(l2));
                float v1 = __half2float(__high2half(h2)) + __half2float(__high2half(l2));
                o0 = fmaf(v0, w4s[k * 3],     fmaf(v1, w4s[k * 3 + 3], o0));
                o1 = fmaf(v0, w4s[k * 3 + 1], fmaf(v1, w4s[k * 3 + 4], o1));
                o2 = fmaf(v0, w4s[k * 3 + 2], fmaf(v1, w4s[k * 3 + 5], o2));
            }
            part[tid * 3] = o0; part[tid * 3 + 1] = o1; part[tid * 3 + 2] = o2;
        }
        __syncthreads();
        if (tid < 192) {
            const int px = tid / 3, j = tid - 3 * px;
            float o = part[(px * 4) * 3 + j] + part[(px * 4 + 1) * 3 + j] +
                      part[(px * 4 + 2) * 3 + j] + part[(px * 4 + 3) * 3 + j] + b4[j];
            if (sidx != 0)
                o = fmaf(o, cscal[sidx * 3 + j], cshft[sidx * 3 + j]);
            out[(p0 + px) * 3 + j] = o;
        }
    }
}

extern "C" void kernel_launch(void* const* d_in, const int* in_sizes, int n_in,
                              void* d_out, int out_size)
{
    (void)in_sizes; (void)n_in; (void)out_size;
    const float* x      = (const float*)d_in[0];
    const int*   sidx   = (const int*)  d_in[1];
    const float* shiftv = (const float*)d_in[2];
    const float* rotang = (const float*)d_in[3];
    const float* cscal  = (const float*)d_in[4];
    const float* cshft  = (const float*)d_in[5];
    const float* W1 = (const float*)d_in[6];
    const float* b1 = (const float*)d_in[7];
    const float* W2 = (const float*)d_in[8];
    const float* b2 = (const float*)d_in[9];
    const float* W3 = (const float*)d_in[10];
    const float* b3 = (const float*)d_in[11];
    const float* W4 = (const float*)d_in[12];
    const float* b4 = (const float*)d_in[13];
    float* out = (float*)d_out;

    int nsm = 0;
    cudaDeviceGetAttribute(&nsm, cudaDevAttrMultiProcessorCount, 0);
    if (nsm <= 0) nsm = 148;
    if (nsm > NTILES) nsm = NTILES;

    prep_kernel<<<512, 256>>>(W2, W3);

    cudaFuncSetAttribute(inr_hmma_kernel,
                         cudaFuncAttributeMaxDynamicSharedMemorySize, SMEM_ALLOC);
    inr_hmma_kernel<<<nsm, NTHR, SMEM_ALLOC>>>(
        x, sidx, shiftv, rotang, cscal, cshft, W1, b1, b2, b3, W4, b4, out);
}

// round 5
// speedup vs baseline: 3.1746x; 1.2731x over previous
#include <cuda_runtime.h>
#include <cuda_fp16.h>
#include <cstdint>
#include <math.h>

#define NTHR 256
#define NTILES 2048                  // 128 pixels per tile
#define OUT_PIX (16*128*128*3)

// ---- smem byte offsets ----
#define OFF_STAGE(s) ((s)*40960)     // 2 stages: Whi 20480 + Wlo 20480
#define W_LO_OFF 20480
#define OFF_AH  81920                // A hi: [128 m][256 k] fp16, 512B rows, XOR-swizzled 16B chunks
#define OFF_AL  147456               // A lo
#define OFF_W1A 212992
#define OFF_W1B 214016
#define OFF_B1  215040
#define OFF_B2  216064
#define OFF_B3  217088
#define OFF_W4  218112               // float[768]
#define OFF_PART 221184              // float[256*3]
#define OFF_MB  224256               // F0,F1,U0,U1
#define MB_F(s) (OFF_MB + (s)*8)
#define MB_U(s) (OFF_MB + 16 + (s)*8)
#define SMEM_ALLOC 224384

// Pre-split weight images: [layer][hi/lo][kchunk(8 x k32)][256 n x 80B rows]
__device__ __align__(16) unsigned char g_W[2][2][8][20480];

// ---- helpers ----
__device__ __forceinline__ uint32_t smem_u32(const void* p) {
    uint32_t a;
    asm("{ .reg .u64 t; cvta.to.shared.u64 t, %1; cvt.u32.u64 %0, t; }" : "=r"(a) : "l"(p));
    return a;
}
#define MBAR_INIT(mbar, cnt) \
    asm volatile("mbarrier.init.shared.b64 [%0], %1;" :: "r"((uint32_t)(mbar)), "r"((uint32_t)(cnt)) : "memory")
#define MBAR_EXPECT_TX(mbar, tx) \
    asm volatile("mbarrier.arrive.expect_tx.shared.b64 _, [%0], %1;" :: "r"((uint32_t)(mbar)), "r"((uint32_t)(tx)) : "memory")
#define MBAR_ARRIVE(mbar) \
    asm volatile("mbarrier.arrive.shared.b64 _, [%0];" :: "r"((uint32_t)(mbar)) : "memory")

__device__ __forceinline__ void mbar_wait(uint32_t mbar, uint32_t parity) {
    uint32_t done;
    asm volatile("{\n\t.reg .pred p;\n\t"
                 "mbarrier.try_wait.parity.acquire.cta.shared::cta.b64 p, [%1], %2;\n\t"
                 "selp.b32 %0, 1, 0, p;\n\t}" : "=r"(done) : "r"(mbar), "r"(parity) : "memory");
    if (!done) {
        asm volatile("{\n\t.reg .pred P1;\n\t"
                     "W_%=:\n\t"
                     "mbarrier.try_wait.parity.acquire.cta.shared::cta.b64 P1, [%0], %1, 0x989680;\n\t"
                     "@P1 bra.uni D_%=;\n\t"
                     "bra.uni W_%=;\n\t"
                     "D_%=:\n\t}" :: "r"(mbar), "r"(parity) : "memory");
    }
}
__device__ __forceinline__ void bulk_ld(uint32_t dst, const void* src, uint32_t bytes, uint32_t mbar) {
    asm volatile("cp.async.bulk.shared::cluster.global.mbarrier::complete_tx::bytes [%0], [%1], %2, [%3];"
                 :: "r"(dst), "l"(src), "r"(bytes), "r"(mbar) : "memory");
}
#define LDSM4(r, addr) \
    asm volatile("ldmatrix.sync.aligned.m8n8.x4.shared.b16 {%0,%1,%2,%3}, [%4];" \
        : "=r"((r)[0]), "=r"((r)[1]), "=r"((r)[2]), "=r"((r)[3]) : "r"(addr))
#define MMA4(dd, a, b0_, b1_) \
    asm volatile("mma.sync.aligned.m16n8k16.row.col.f32.f16.f16.f32 " \
        "{%0,%1,%2,%3}, {%4,%5,%6,%7}, {%8,%9}, {%0,%1,%2,%3};" \
        : "+f"((dd)[0]), "+f"((dd)[1]), "+f"((dd)[2]), "+f"((dd)[3]) \
        : "r"((a)[0]), "r"((a)[1]), "r"((a)[2]), "r"((a)[3]), "r"(b0_), "r"(b1_))

// A smem address: [m][k] fp16, 512B rows, physical 16B chunk = (k/8) ^ (m&7)
__device__ __forceinline__ uint32_t a_addr(uint32_t base, int m, int k) {
    return base + (uint32_t)(m * 512) +
           (uint32_t)(((((k >> 3) ^ (m & 7))) << 4) + ((k & 7) << 1));
}
__device__ __forceinline__ void store_split(unsigned char* sm, int m, int n, float v0, float v1) {
    __half h0 = __float2half_rn(v0), h1 = __float2half_rn(v1);
    __half l0 = __float2half_rn(v0 - __half2float(h0));
    __half l1 = __float2half_rn(v1 - __half2float(h1));
    *(__half2*)(sm + a_addr(OFF_AH, m, n)) = __halves2half2(h0, h1);
    *(__half2*)(sm + a_addr(OFF_AL, m, n)) = __halves2half2(l0, l1);
}

// ---- prep: split W2/W3 into fp16 hi/lo [n][k] images, 80B rows ----
__global__ void prep_kernel(const float* __restrict__ W2, const float* __restrict__ W3) {
    int idx = blockIdx.x * blockDim.x + threadIdx.x;   // 0..131071
    int l = idx >> 16, r = idx & 65535;
    int k = r >> 8, n = r & 255;
    float w = (l ? W3 : W2)[k * 256 + n];
    __half h = __float2half_rn(w);
    __half lo = __float2half_rn(w - __half2float(h));
    int kc = k >> 5, kk = k & 31;
    *(__half*)&g_W[l][0][kc][n * 80 + kk * 2] = h;
    *(__half*)&g_W[l][1][kc][n * 80 + kk * 2] = lo;
}

__device__ __forceinline__ void issue_load(uint32_t smb, int g) {
    const int lc = g & 15;                    // 16 chunks per tile (8 per layer x 2 layers)
    const int l = lc >> 3, kc = lc & 7, s = g & 1;
    const uint32_t mb = smb + MB_F(s);
    const uint32_t dst = smb + OFF_STAGE(s);
    MBAR_EXPECT_TX(mb, 40960);
    bulk_ld(dst,            &g_W[l][0][kc][0], 20480, mb);
    bulk_ld(dst + W_LO_OFF, &g_W[l][1][kc][0], 20480, mb);
}

// one 256->256 layer for 128 pixels: warp tile 64x64, 3-term split HMMA
__device__ __forceinline__ void run_layer(
    float (&d)[4][8][4], uint32_t smb, int m0, int n0,
    int lane, int tid, int& g, int total_chunks)
{
    const int aRow = (lane & 7) + ((lane >> 3) & 1) * 8;   // ldmatrix A row-in-tile
    const int aCs  = lane >> 4;                            // A k8-chunk select
    const int wRow = ((lane >> 4) & 1) * 8 + (lane & 7);   // ldmatrix B row (n)
    const int wCs  = (lane >> 3) & 1;                      // B k8-chunk select

    for (int kc = 0; kc < 8; kc++) {
        const int s = g & 1;
        const uint32_t ph = (uint32_t)((g >> 1) & 1);
        mbar_wait(smb + MB_F(s), ph);
        const uint32_t stH = smb + OFF_STAGE(s);
        const uint32_t stL = stH + W_LO_OFF;
#pragma unroll
        for (int ks = 0; ks < 2; ks++) {
            const int cb = kc * 4 + ks * 2 + aCs;          // A 16B-chunk index
            uint32_t ah[4][4], al[4][4];
#pragma unroll
            for (int mt = 0; mt < 4; mt++) {
                const int mA = m0 + mt * 16 + aRow;
                const uint32_t co = (uint32_t)((cb ^ (mA & 7)) << 4);
                LDSM4(ah[mt], smb + OFF_AH + (uint32_t)(mA * 512) + co);
                LDSM4(al[mt], smb + OFF_AL + (uint32_t)(mA * 512) + co);
            }
            const uint32_t wko = (uint32_t)((ks * 2 + wCs) << 4);
#pragma unroll
            for (int np = 0; np < 4; np++) {
                const uint32_t wro = (uint32_t)((n0 + np * 16 + wRow) * 80) + wko;
                uint32_t wh[4], wl[4];
                LDSM4(wh, stH + wro);
                LDSM4(wl, stL + wro);
#pragma unroll
                for (int mt = 0; mt < 4; mt++) {
                    MMA4(d[mt][np*2],   ah[mt], wh[0], wh[1]);
                    MMA4(d[mt][np*2],   al[mt], wh[0], wh[1]);
                    MMA4(d[mt][np*2],   ah[mt], wl[0], wl[1]);
                    MMA4(d[mt][np*2+1], ah[mt], wh[2], wh[3]);
                    MMA4(d[mt][np*2+1], al[mt], wh[2], wh[3]);
                    MMA4(d[mt][np*2+1], ah[mt], wl[2], wl[3]);
                }
            }
        }
        MBAR_ARRIVE(smb + MB_U(s));                        // all 256 threads
        if (tid == 0 && g + 2 < total_chunks) {
            mbar_wait(smb + MB_U(s), ph);                  // stage fully consumed
            issue_load(smb, g + 2);
        }
        g++;
    }
}

__device__ __forceinline__ void epi_store(
    unsigned char* sm, float (&d)[4][8][4], const float* bias,
    int m0, int n0, int qm, int qn)
{
#pragma unroll
    for (int mt = 0; mt < 4; mt++) {
        const int mA = m0 + mt * 16 + qm;
#pragma unroll
        for (int nt = 0; nt < 8; nt++) {
            const int n = n0 + nt * 8 + qn;
            const float bb0 = bias[n], bb1 = bias[n + 1];
            store_split(sm, mA,     n, fmaxf(d[mt][nt][0] + bb0, 0.f), fmaxf(d[mt][nt][1] + bb1, 0.f));
            store_split(sm, mA + 8, n, fmaxf(d[mt][nt][2] + bb0, 0.f), fmaxf(d[mt][nt][3] + bb1, 0.f));
        }
    }
}

__global__ void __launch_bounds__(NTHR, 1) inr_hmma_kernel(
    const float* __restrict__ x, const int* __restrict__ sample_idx,
    const float* __restrict__ shiftv, const float* __restrict__ rotang,
    const float* __restrict__ cscal, const float* __restrict__ cshft,
    const float* __restrict__ W1, const float* __restrict__ b1,
    const float* __restrict__ b2, const float* __restrict__ b3,
    const float* __restrict__ W4, const float* __restrict__ b4,
    float* __restrict__ out)
{
    extern __shared__ __align__(128) unsigned char sm[];
    const uint32_t smb = smem_u32(sm);

    const int tid = threadIdx.x;
    const int lane = tid & 31, wid = tid >> 5;
    const int m0 = (wid & 1) * 64, n0 = (wid >> 1) * 64;    // warp tile 64x64
    const int qm = lane >> 2, qn = (lane & 3) * 2;

    float* w1a = (float*)(sm + OFF_W1A);
    float* w1b = (float*)(sm + OFF_W1B);
    float* b1v = (float*)(sm + OFF_B1);
    float* b2v = (float*)(sm + OFF_B2);
    float* b3v = (float*)(sm + OFF_B3);
    float* w4s = (float*)(sm + OFF_W4);
    float* part = (float*)(sm + OFF_PART);

    w1a[tid] = W1[tid]; w1b[tid] = W1[256 + tid];
    b1v[tid] = b1[tid]; b2v[tid] = b2[tid]; b3v[tid] = b3[tid];
    w4s[tid] = W4[tid]; w4s[tid + 256] = W4[tid + 256]; w4s[tid + 512] = W4[tid + 512];
    if (tid == 0) {
        MBAR_INIT(smb + MB_F(0), 1);   MBAR_INIT(smb + MB_F(1), 1);
        MBAR_INIT(smb + MB_U(0), NTHR); MBAR_INIT(smb + MB_U(1), NTHR);
    }
    __syncthreads();

    const int bid = blockIdx.x, grid = gridDim.x;
    const int ntiles = (NTILES - 1 - bid) / grid + 1;
    const int total_chunks = ntiles * 16;
    int g = 0;
    if (tid == 0) { issue_load(smb, 0); issue_load(smb, 1); }

    const float2* x2 = (const float2*)x;

    for (int t = bid; t < NTILES; t += grid) {
        const int b = t >> 7;                 // 128 tiles per batch
        const int p0 = t * 128;
        const int sidx = sample_idx[b];
        const float dyv = shiftv[sidx * 2], dxv = shiftv[sidx * 2 + 1];
        float sv, cvv;
        sincosf(rotang[sidx], &sv, &cvv);

        // ---- layer 1 (SIMT) -> A hi/lo smem: 2 threads per pixel, 128 n each ----
        {
            const int px = tid >> 1, q = tid & 1;
            float2 xv = x2[p0 + px];
            const float c0 = cvv * xv.x - sv * xv.y + dxv;
            const float c1 = sv * xv.x + cvv * xv.y + dyv;
#pragma unroll
            for (int i = 0; i < 64; i++) {
                const int n = q * 128 + i * 2;
                float h0 = fmaxf(fmaf(c0, w1a[n],     fmaf(c1, w1b[n],     b1v[n])),     0.f);
                float h1 = fmaxf(fmaf(c0, w1a[n + 1], fmaf(c1, w1b[n + 1], b1v[n + 1])), 0.f);
                store_split(sm, px, n, h0, h1);
            }
            if (tid == 255 && (t & 127) == 0) {
                out[OUT_PIX + b] = dxv;
                out[OUT_PIX + 16 + b] = dyv;
            }
        }
        __syncthreads();

        float d[4][8][4];
#pragma unroll
        for (int i = 0; i < 4; i++)
#pragma unroll
            for (int j = 0; j < 8; j++)
#pragma unroll
                for (int kq = 0; kq < 4; kq++) d[i][j][kq] = 0.f;
        run_layer(d, smb, m0, n0, lane, tid, g, total_chunks);   // layer 2
        __syncthreads();
        epi_store(sm, d, b2v, m0, n0, qm, qn);
        __syncthreads();

#pragma unroll
        for (int i = 0; i < 4; i++)
#pragma unroll
            for (int j = 0; j < 8; j++)
#pragma unroll
                for (int kq = 0; kq < 4; kq++) d[i][j][kq] = 0.f;
        run_layer(d, smb, m0, n0, lane, tid, g, total_chunks);   // layer 3
        __syncthreads();
        epi_store(sm, d, b3v, m0, n0, qm, qn);
        __syncthreads();

        // ---- layer 4: 2 threads per pixel, 128 k each ----
        {
            const int px = tid >> 1, q = tid & 1;
            float o0 = 0.f, o1 = 0.f, o2 = 0.f;
#pragma unroll 8
            for (int kk = 0; kk < 128; kk += 2) {
                const int k = q * 128 + kk;
                uint32_t ah = *(const uint32_t*)(sm + a_addr(OFF_AH, px, k));
                uint32_t al = *(const uint32_t*)(sm + a_addr(OFF_AL, px, k));
                __half2 h2 = *(__half2*)&ah, l2 = *(__half2*)&al;
                float v0 = __half2float(__low2half(h2))  + __half2float(__low2half(l2));
                float v1 = __half2float(__high2half(h2)) + __half2float(__high2half(l2));
                o0 = fmaf(v0, w4s[k * 3],     fmaf(v1, w4s[k * 3 + 3], o0));
                o1 = fmaf(v0, w4s[k * 3 + 1], fmaf(v1, w4s[k * 3 + 4], o1));
                o2 = fmaf(v0, w4s[k * 3 + 2], fmaf(v1, w4s[k * 3 + 5], o2));
            }
            part[tid * 3] = o0; part[tid * 3 + 1] = o1; part[tid * 3 + 2] = o2;
        }
        __syncthreads();
        {
            const int px = tid >> 1, q = tid & 1;    // 2 threads finalize alternating components? no:
            // finalize: thread with q==0 does all 3 components of its pixel
            if (q == 0) {
#pragma unroll
                for (int j = 0; j < 3; j++) {
                    float o = part[(2 * px) * 3 + j] + part[(2 * px + 1) * 3 + j] + b4[j];
                    if (sidx != 0)
                        o = fmaf(o, cscal[sidx * 3 + j], cshft[sidx * 3 + j]);
                    out[(p0 + px) * 3 + j] = o;
                }
            }
        }
        __syncthreads();   // protect part[] and A smem before next tile overwrites
    }
}

extern "C" void kernel_launch(void* const* d_in, const int* in_sizes, int n_in,
                              void* d_out, int out_size)
{
    (void)in_sizes; (void)n_in; (void)out_size;
    const float* x      = (const float*)d_in[0];
    const int*   sidx   = (const int*)  d_in[1];
    const float* shiftv = (const float*)d_in[2];
    const float* rotang = (const float*)d_in[3];
    const float* cscal  = (const float*)d_in[4];
    const float* cshft  = (const float*)d_in[5];
    const float* W1 = (const float*)d_in[6];
    const float* b1 = (const float*)d_in[7];
    const float* W2 = (const float*)d_in[8];
    const float* b2 = (const float*)d_in[9];
    const float* W3 = (const float*)d_in[10];
    const float* b3 = (const float*)d_in[11];
    const float* W4 = (const float*)d_in[12];
    const float* b4 = (const float*)d_in[13];
    float* out = (float*)d_out;

    int nsm = 0;
    cudaDeviceGetAttribute(&nsm, cudaDevAttrMultiProcessorCount, 0);
    if (nsm <= 0) nsm = 148;
    if (nsm > NTILES) nsm = NTILES;

    prep_kernel<<<512, 256>>>(W2, W3);

    cudaFuncSetAttribute(inr_hmma_kernel,
                         cudaFuncAttributeMaxDynamicSharedMemorySize, SMEM_ALLOC);
    inr_hmma_kernel<<<nsm, NTHR, SMEM_ALLOC>>>(
        x, sidx, shiftv, rotang, cscal, cshft, W1, b1, b2, b3, W4, b4, out);
}

// round 6
// speedup vs baseline: 3.2910x; 1.0367x over previous
#include <cuda_runtime.h>
#include <cuda_fp16.h>
#include <cstdint>
#include <math.h>

#define NTHR 256
#define NTILES 2048                  // 128 pixels per tile
#define OUT_PIX (16*128*128*3)

// ---- smem byte offsets ----
#define OFF_STAGE(s) ((s)*40960)     // 2 stages: Whi 20480 + Wlo 20480
#define W_LO_OFF 20480
#define OFF_AH  81920                // A hi: [128 m][256 k] fp16, 512B rows, XOR-swizzled 16B chunks
#define OFF_AL  147456               // A lo
#define OFF_W1A 212992
#define OFF_W1B 214016
#define OFF_B1  215040
#define OFF_B2  216064
#define OFF_B3  217088
#define OFF_W4  218112               // float[768]
#define OFF_PART 221184              // float[4][128][3] layer-4 partials (6144 B)
#define OFF_MB  227328               // F0,F1,U0,U1
#define MB_F(s) (OFF_MB + (s)*8)
#define MB_U(s) (OFF_MB + 16 + (s)*8)
#define SMEM_ALLOC 227456

// Pre-split weight images: [layer][hi/lo][kchunk(8 x k32)][256 n x 80B rows]
__device__ __align__(16) unsigned char g_W[2][2][8][20480];

// ---- helpers ----
__device__ __forceinline__ uint32_t smem_u32(const void* p) {
    uint32_t a;
    asm("{ .reg .u64 t; cvta.to.shared.u64 t, %1; cvt.u32.u64 %0, t; }" : "=r"(a) : "l"(p));
    return a;
}
#define MBAR_INIT(mbar, cnt) \
    asm volatile("mbarrier.init.shared.b64 [%0], %1;" :: "r"((uint32_t)(mbar)), "r"((uint32_t)(cnt)) : "memory")
#define MBAR_EXPECT_TX(mbar, tx) \
    asm volatile("mbarrier.arrive.expect_tx.shared.b64 _, [%0], %1;" :: "r"((uint32_t)(mbar)), "r"((uint32_t)(tx)) : "memory")
#define MBAR_ARRIVE(mbar) \
    asm volatile("mbarrier.arrive.shared.b64 _, [%0];" :: "r"((uint32_t)(mbar)) : "memory")

__device__ __forceinline__ void mbar_wait(uint32_t mbar, uint32_t parity) {
    uint32_t done;
    asm volatile("{\n\t.reg .pred p;\n\t"
                 "mbarrier.try_wait.parity.acquire.cta.shared::cta.b64 p, [%1], %2;\n\t"
                 "selp.b32 %0, 1, 0, p;\n\t}" : "=r"(done) : "r"(mbar), "r"(parity) : "memory");
    if (!done) {
        asm volatile("{\n\t.reg .pred P1;\n\t"
                     "W_%=:\n\t"
                     "mbarrier.try_wait.parity.acquire.cta.shared::cta.b64 P1, [%0], %1, 0x989680;\n\t"
                     "@P1 bra.uni D_%=;\n\t"
                     "bra.uni W_%=;\n\t"
                     "D_%=:\n\t}" :: "r"(mbar), "r"(parity) : "memory");
    }
}
__device__ __forceinline__ void bulk_ld(uint32_t dst, const void* src, uint32_t bytes, uint32_t mbar) {
    asm volatile("cp.async.bulk.shared::cluster.global.mbarrier::complete_tx::bytes [%0], [%1], %2, [%3];"
                 :: "r"(dst), "l"(src), "r"(bytes), "r"(mbar) : "memory");
}
#define LDSM4(r, addr) \
    asm volatile("ldmatrix.sync.aligned.m8n8.x4.shared.b16 {%0,%1,%2,%3}, [%4];" \
        : "=r"((r)[0]), "=r"((r)[1]), "=r"((r)[2]), "=r"((r)[3]) : "r"(addr))
#define MMA4(dd, a, b0_, b1_) \
    asm volatile("mma.sync.aligned.m16n8k16.row.col.f32.f16.f16.f32 " \
        "{%0,%1,%2,%3}, {%4,%5,%6,%7}, {%8,%9}, {%0,%1,%2,%3};" \
        : "+f"((dd)[0]), "+f"((dd)[1]), "+f"((dd)[2]), "+f"((dd)[3]) \
        : "r"((a)[0]), "r"((a)[1]), "r"((a)[2]), "r"((a)[3]), "r"(b0_), "r"(b1_))

// A smem address: [m][k] fp16, 512B rows, physical 16B chunk = (k/8) ^ (m&7)
__device__ __forceinline__ uint32_t a_addr(uint32_t base, int m, int k) {
    return base + (uint32_t)(m * 512) +
           (uint32_t)(((((k >> 3) ^ (m & 7))) << 4) + ((k & 7) << 1));
}
// packed hi/lo split store (one F2FP.PACK per half2)
__device__ __forceinline__ void store_split(unsigned char* sm, int m, int n, float v0, float v1) {
    __half2 h2 = __float22half2_rn(make_float2(v0, v1));
    float2 hf = __half22float2(h2);
    __half2 l2 = __float22half2_rn(make_float2(v0 - hf.x, v1 - hf.y));
    *(__half2*)(sm + a_addr(OFF_AH, m, n)) = h2;
    *(__half2*)(sm + a_addr(OFF_AL, m, n)) = l2;
}

// ---- prep: split W2/W3 into fp16 hi/lo [n][k] images, 80B rows ----
__global__ void prep_kernel(const float* __restrict__ W2, const float* __restrict__ W3) {
    int idx = blockIdx.x * blockDim.x + threadIdx.x;   // 0..131071
    int l = idx >> 16, r = idx & 65535;
    int k = r >> 8, n = r & 255;
    float w = (l ? W3 : W2)[k * 256 + n];
    __half h = __float2half_rn(w);
    __half lo = __float2half_rn(w - __half2float(h));
    int kc = k >> 5, kk = k & 31;
    *(__half*)&g_W[l][0][kc][n * 80 + kk * 2] = h;
    *(__half*)&g_W[l][1][kc][n * 80 + kk * 2] = lo;
}

__device__ __forceinline__ void issue_load(uint32_t smb, int g) {
    const int lc = g & 15;                    // 16 chunks per tile (8 per layer x 2 layers)
    const int l = lc >> 3, kc = lc & 7, s = g & 1;
    const uint32_t mb = smb + MB_F(s);
    const uint32_t dst = smb + OFF_STAGE(s);
    MBAR_EXPECT_TX(mb, 40960);
    bulk_ld(dst,            &g_W[l][0][kc][0], 20480, mb);
    bulk_ld(dst + W_LO_OFF, &g_W[l][1][kc][0], 20480, mb);
}

// one 256->256 layer for 128 pixels: warp tile 64x64, 3-term split HMMA
__device__ __forceinline__ void run_layer(
    float (&d)[4][8][4], uint32_t smb, int m0, int n0,
    int lane, int tid, int& g, int total_chunks)
{
    const int aRow = (lane & 7) + ((lane >> 3) & 1) * 8;   // ldmatrix A row-in-tile
    const int aCs  = lane >> 4;                            // A k8-chunk select
    const int wRow = ((lane >> 4) & 1) * 8 + (lane & 7);   // ldmatrix B row (n)
    const int wCs  = (lane >> 3) & 1;                      // B k8-chunk select

    for (int kc = 0; kc < 8; kc++) {
        const int s = g & 1;
        const uint32_t ph = (uint32_t)((g >> 1) & 1);
        mbar_wait(smb + MB_F(s), ph);
        const uint32_t stH = smb + OFF_STAGE(s);
        const uint32_t stL = stH + W_LO_OFF;
#pragma unroll
        for (int ks = 0; ks < 2; ks++) {
            const int cb = kc * 4 + ks * 2 + aCs;          // A 16B-chunk index
            uint32_t ah[4][4], al[4][4];
#pragma unroll
            for (int mt = 0; mt < 4; mt++) {
                const int mA = m0 + mt * 16 + aRow;
                const uint32_t co = (uint32_t)((cb ^ (mA & 7)) << 4);
                LDSM4(ah[mt], smb + OFF_AH + (uint32_t)(mA * 512) + co);
                LDSM4(al[mt], smb + OFF_AL + (uint32_t)(mA * 512) + co);
            }
            const uint32_t wko = (uint32_t)((ks * 2 + wCs) << 4);
#pragma unroll
            for (int np = 0; np < 4; np++) {
                const uint32_t wro = (uint32_t)((n0 + np * 16 + wRow) * 80) + wko;
                uint32_t wh[4], wl[4];
                LDSM4(wh, stH + wro);
                LDSM4(wl, stL + wro);
#pragma unroll
                for (int mt = 0; mt < 4; mt++) {
                    MMA4(d[mt][np*2],   ah[mt], wh[0], wh[1]);
                    MMA4(d[mt][np*2],   al[mt], wh[0], wh[1]);
                    MMA4(d[mt][np*2],   ah[mt], wl[0], wl[1]);
                    MMA4(d[mt][np*2+1], ah[mt], wh[2], wh[3]);
                    MMA4(d[mt][np*2+1], al[mt], wh[2], wh[3]);
                    MMA4(d[mt][np*2+1], ah[mt], wl[2], wl[3]);
                }
            }
        }
        if (lane == 0) MBAR_ARRIVE(smb + MB_U(s));         // per-warp arrive (count 8)
        if (tid == 0 && g + 2 < total_chunks) {
            mbar_wait(smb + MB_U(s), ph);                  // stage fully consumed
            issue_load(smb, g + 2);
        }
        g++;
    }
}

// layer-2 epilogue: bias+relu, packed split back to A smem
__device__ __forceinline__ void epi_store(
    unsigned char* sm, float (&d)[4][8][4], const float* bias,
    int m0, int n0, int qm, int qn)
{
#pragma unroll
    for (int mt = 0; mt < 4; mt++) {
        const int mA = m0 + mt * 16 + qm;
#pragma unroll
        for (int nt = 0; nt < 8; nt++) {
            const int n = n0 + nt * 8 + qn;
            const float bb0 = bias[n], bb1 = bias[n + 1];
            store_split(sm, mA,     n, fmaxf(d[mt][nt][0] + bb0, 0.f), fmaxf(d[mt][nt][1] + bb1, 0.f));
            store_split(sm, mA + 8, n, fmaxf(d[mt][nt][2] + bb0, 0.f), fmaxf(d[mt][nt][3] + bb1, 0.f));
        }
    }
}

// layer-3 epilogue fused with layer-4: relu(d+b3) dotted with W4 straight from
// fragments; shfl-reduce over the 4 qn-lanes; partial per n0-group into smem.
__device__ __forceinline__ void epi3_fuse(
    float (&d)[4][8][4], const float* b3v, const float* w4s, float* part,
    int m0, int n0, int wid, int lane, int qm, int qn)
{
    const int n0g = wid >> 1;
#pragma unroll
    for (int mt = 0; mt < 4; mt++) {
        float oo[2][3];
#pragma unroll
        for (int h = 0; h < 2; h++)
#pragma unroll
            for (int j = 0; j < 3; j++) oo[h][j] = 0.f;
#pragma unroll
        for (int nt = 0; nt < 8; nt++) {
            const int n = n0 + nt * 8 + qn;
            const float2 bb = *(const float2*)&b3v[n];
            const float2 wA = *(const float2*)&w4s[n * 3];
            const float2 wB = *(const float2*)&w4s[n * 3 + 2];
            const float2 wC = *(const float2*)&w4s[n * 3 + 4];
            // n:   w4 = {wA.x, wA.y, wB.x};  n+1: w4 = {wB.y, wC.x, wC.y}
            float v0 = fmaxf(d[mt][nt][0] + bb.x, 0.f);
            float v1 = fmaxf(d[mt][nt][1] + bb.y, 0.f);
            float v2 = fmaxf(d[mt][nt][2] + bb.x, 0.f);
            float v3 = fmaxf(d[mt][nt][3] + bb.y, 0.f);
            oo[0][0] = fmaf(v0, wA.x, fmaf(v1, wB.y, oo[0][0]));
            oo[0][1] = fmaf(v0, wA.y, fmaf(v1, wC.x, oo[0][1]));
            oo[0][2] = fmaf(v0, wB.x, fmaf(v1, wC.y, oo[0][2]));
            oo[1][0] = fmaf(v2, wA.x, fmaf(v3, wB.y, oo[1][0]));
            oo[1][1] = fmaf(v2, wA.y, fmaf(v3, wC.x, oo[1][1]));
            oo[1][2] = fmaf(v2, wB.x, fmaf(v3, wC.y, oo[1][2]));
        }
        // reduce across qn lanes (lane&3)
#pragma unroll
        for (int h = 0; h < 2; h++)
#pragma unroll
            for (int j = 0; j < 3; j++) {
                float v = oo[h][j];
                v += __shfl_xor_sync(0xFFFFFFFFu, v, 1);
                v += __shfl_xor_sync(0xFFFFFFFFu, v, 2);
                oo[h][j] = v;
            }
        if ((lane & 3) == 0) {
#pragma unroll
            for (int h = 0; h < 2; h++) {
                const int row = m0 + mt * 16 + h * 8 + qm;
#pragma unroll
                for (int j = 0; j < 3; j++)
                    part[n0g * 384 + row * 3 + j] = oo[h][j];
            }
        }
    }
}

__global__ void __launch_bounds__(NTHR, 1) inr_hmma_kernel(
    const float* __restrict__ x, const int* __restrict__ sample_idx,
    const float* __restrict__ shiftv, const float* __restrict__ rotang,
    const float* __restrict__ cscal, const float* __restrict__ cshft,
    const float* __restrict__ W1, const float* __restrict__ b1,
    const float* __restrict__ b2, const float* __restrict__ b3,
    const float* __restrict__ W4, const float* __restrict__ b4,
    float* __restrict__ out)
{
    extern __shared__ __align__(128) unsigned char sm[];
    const uint32_t smb = smem_u32(sm);

    const int tid = threadIdx.x;
    const int lane = tid & 31, wid = tid >> 5;
    const int m0 = (wid & 1) * 64, n0 = (wid >> 1) * 64;    // warp tile 64x64
    const int qm = lane >> 2, qn = (lane & 3) * 2;

    float* w1a = (float*)(sm + OFF_W1A);
    float* w1b = (float*)(sm + OFF_W1B);
    float* b1v = (float*)(sm + OFF_B1);
    float* b2v = (float*)(sm + OFF_B2);
    float* b3v = (float*)(sm + OFF_B3);
    float* w4s = (float*)(sm + OFF_W4);
    float* part = (float*)(sm + OFF_PART);

    w1a[tid] = W1[tid]; w1b[tid] = W1[256 + tid];
    b1v[tid] = b1[tid]; b2v[tid] = b2[tid]; b3v[tid] = b3[tid];
    w4s[tid] = W4[tid]; w4s[tid + 256] = W4[tid + 256]; w4s[tid + 512] = W4[tid + 512];
    if (tid == 0) {
        MBAR_INIT(smb + MB_F(0), 1); MBAR_INIT(smb + MB_F(1), 1);
        MBAR_INIT(smb + MB_U(0), 8); MBAR_INIT(smb + MB_U(1), 8);
    }
    __syncthreads();

    const int bid = blockIdx.x, grid = gridDim.x;
    const int ntiles = (NTILES - 1 - bid) / grid + 1;
    const int total_chunks = ntiles * 16;
    int g = 0;
    if (tid == 0) { issue_load(smb, 0); issue_load(smb, 1); }

    const float2* x2 = (const float2*)x;

    for (int t = bid; t < NTILES; t += grid) {
        const int b = t >> 7;                 // 128 tiles per batch
        const int p0 = t * 128;
        const int sidx = sample_idx[b];
        const float dyv = shiftv[sidx * 2], dxv = shiftv[sidx * 2 + 1];
        float sv, cvv;
        sincosf(rotang[sidx], &sv, &cvv);

        // ---- layer 1 (SIMT) -> A hi/lo smem: 2 threads per pixel, 128 n each ----
        {
            const int px = tid >> 1, q = tid & 1;
            float2 xv = x2[p0 + px];
            const float c0 = cvv * xv.x - sv * xv.y + dxv;
            const float c1 = sv * xv.x + cvv * xv.y + dyv;
#pragma unroll
            for (int i = 0; i < 64; i++) {
                const int n = q * 128 + i * 2;
                float h0 = fmaxf(fmaf(c0, w1a[n],     fmaf(c1, w1b[n],     b1v[n])),     0.f);
                float h1 = fmaxf(fmaf(c0, w1a[n + 1], fmaf(c1, w1b[n + 1], b1v[n + 1])), 0.f);
                store_split(sm, px, n, h0, h1);
            }
            if (tid == 255 && (t & 127) == 0) {
                out[OUT_PIX + b] = dxv;
                out[OUT_PIX + 16 + b] = dyv;
            }
        }
        __syncthreads();

        float d[4][8][4];
#pragma unroll
        for (int i = 0; i < 4; i++)
#pragma unroll
            for (int j = 0; j < 8; j++)
#pragma unroll
                for (int kq = 0; kq < 4; kq++) d[i][j][kq] = 0.f;
        run_layer(d, smb, m0, n0, lane, tid, g, total_chunks);   // layer 2
        __syncthreads();
        epi_store(sm, d, b2v, m0, n0, qm, qn);
        __syncthreads();

#pragma unroll
        for (int i = 0; i < 4; i++)
#pragma unroll
            for (int j = 0; j < 8; j++)
#pragma unroll
                for (int kq = 0; kq < 4; kq++) d[i][j][kq] = 0.f;
        run_layer(d, smb, m0, n0, lane, tid, g, total_chunks);   // layer 3
        epi3_fuse(d, b3v, w4s, part, m0, n0, wid, lane, qm, qn); // fused layer 4 partials
        __syncthreads();

        // ---- final reduce: 4 n0-group partials + bias + color affine ----
        for (int it = tid; it < 384; it += NTHR) {
            const int px = it / 3, j = it - 3 * px;
            float o = part[px * 3 + j] + part[384 + px * 3 + j] +
                      part[768 + px * 3 + j] + part[1152 + px * 3 + j] + b4[j];
            if (sidx != 0)
                o = fmaf(o, cscal[sidx * 3 + j], cshft[sidx * 3 + j]);
            out[(p0 + px) * 3 + j] = o;
        }
        // no trailing sync needed: next layer-1 writes only A smem, whose last
        // readers (layer-3 MMAs) finished before the post-epi3 sync; part's
        // next writer (epi3) is separated by >=3 syncs.
    }
}

extern "C" void kernel_launch(void* const* d_in, const int* in_sizes, int n_in,
                              void* d_out, int out_size)
{
    (void)in_sizes; (void)n_in; (void)out_size;
    const float* x      = (const float*)d_in[0];
    const int*   sidx   = (const int*)  d_in[1];
    const float* shiftv = (const float*)d_in[2];
    const float* rotang = (const float*)d_in[3];
    const float* cscal  = (const float*)d_in[4];
    const float* cshft  = (const float*)d_in[5];
    const float* W1 = (const float*)d_in[6];
    const float* b1 = (const float*)d_in[7];
    const float* W2 = (const float*)d_in[8];
    const float* b2 = (const float*)d_in[9];
    const float* W3 = (const float*)d_in[10];
    const float* b3 = (const float*)d_in[11];
    const float* W4 = (const float*)d_in[12];
    const float* b4 = (const float*)d_in[13];
    float* out = (float*)d_out;

    int nsm = 0;
    cudaDeviceGetAttribute(&nsm, cudaDevAttrMultiProcessorCount, 0);
    if (nsm <= 0) nsm = 148;
    if (nsm > NTILES) nsm = NTILES;

    prep_kernel<<<512, 256>>>(W2, W3);

    cudaFuncSetAttribute(inr_hmma_kernel,
                         cudaFuncAttributeMaxDynamicSharedMemorySize, SMEM_ALLOC);
    inr_hmma_kernel<<<nsm, NTHR, SMEM_ALLOC>>>(
        x, sidx, shiftv, rotang, cscal, cshft, W1, b1, b2, b3, W4, b4, out);
}

// round 7
// speedup vs baseline: 4.7552x; 1.4449x over previous
#include <cuda_runtime.h>
#include <cuda_fp16.h>
#include <cstdint>
#include <math.h>

#define NTHR 256
#define NTILES 2048                  // 128 pixels per tile
#define OUT_PIX (16*128*128*3)

// ---- smem byte offsets ----
#define OFF_STAGE(s) ((s)*20480)     // 2 stages: W hi only, 20480 each
#define OFF_AH  40960                // A hi: [128 m][256 k] fp16, 512B rows, XOR-swizzled 16B chunks
#define OFF_AL  106496               // A lo
#define OFF_W1A 172032
#define OFF_W1B 173056
#define OFF_B1  174080
#define OFF_B2  175104
#define OFF_B3  176128
#define OFF_W4  177152               // float[768]
#define OFF_PART 180224              // float[4][128][3] layer-4 partials (6144 B)
#define OFF_MB  186368               // F0,F1,U0,U1
#define MB_F(s) (OFF_MB + (s)*8)
#define MB_U(s) (OFF_MB + 16 + (s)*8)
#define SMEM_ALLOC 186496

// Pre-split weight images (hi part only): [layer][kchunk(8 x k32)][256 n x 80B rows]
__device__ __align__(16) unsigned char g_W[2][8][20480];

// ---- helpers ----
__device__ __forceinline__ uint32_t smem_u32(const void* p) {
    uint32_t a;
    asm("{ .reg .u64 t; cvta.to.shared.u64 t, %1; cvt.u32.u64 %0, t; }" : "=r"(a) : "l"(p));
    return a;
}
#define MBAR_INIT(mbar, cnt) \
    asm volatile("mbarrier.init.shared.b64 [%0], %1;" :: "r"((uint32_t)(mbar)), "r"((uint32_t)(cnt)) : "memory")
#define MBAR_EXPECT_TX(mbar, tx) \
    asm volatile("mbarrier.arrive.expect_tx.shared.b64 _, [%0], %1;" :: "r"((uint32_t)(mbar)), "r"((uint32_t)(tx)) : "memory")
#define MBAR_ARRIVE(mbar) \
    asm volatile("mbarrier.arrive.shared.b64 _, [%0];" :: "r"((uint32_t)(mbar)) : "memory")

__device__ __forceinline__ void mbar_wait(uint32_t mbar, uint32_t parity) {
    uint32_t done;
    asm volatile("{\n\t.reg .pred p;\n\t"
                 "mbarrier.try_wait.parity.acquire.cta.shared::cta.b64 p, [%1], %2;\n\t"
                 "selp.b32 %0, 1, 0, p;\n\t}" : "=r"(done) : "r"(mbar), "r"(parity) : "memory");
    if (!done) {
        asm volatile("{\n\t.reg .pred P1;\n\t"
                     "W_%=:\n\t"
                     "mbarrier.try_wait.parity.acquire.cta.shared::cta.b64 P1, [%0], %1, 0x989680;\n\t"
                     "@P1 bra.uni D_%=;\n\t"
                     "bra.uni W_%=;\n\t"
                     "D_%=:\n\t}" :: "r"(mbar), "r"(parity) : "memory");
    }
}
__device__ __forceinline__ void bulk_ld(uint32_t dst, const void* src, uint32_t bytes, uint32_t mbar) {
    asm volatile("cp.async.bulk.shared::cluster.global.mbarrier::complete_tx::bytes [%0], [%1], %2, [%3];"
                 :: "r"(dst), "l"(src), "r"(bytes), "r"(mbar) : "memory");
}
#define LDSM4(r, addr) \
    asm volatile("ldmatrix.sync.aligned.m8n8.x4.shared.b16 {%0,%1,%2,%3}, [%4];" \
        : "=r"((r)[0]), "=r"((r)[1]), "=r"((r)[2]), "=r"((r)[3]) : "r"(addr))
#define MMA4(dd, a, b0_, b1_) \
    asm volatile("mma.sync.aligned.m16n8k16.row.col.f32.f16.f16.f32 " \
        "{%0,%1,%2,%3}, {%4,%5,%6,%7}, {%8,%9}, {%0,%1,%2,%3};" \
        : "+f"((dd)[0]), "+f"((dd)[1]), "+f"((dd)[2]), "+f"((dd)[3]) \
        : "r"((a)[0]), "r"((a)[1]), "r"((a)[2]), "r"((a)[3]), "r"(b0_), "r"(b1_))

// A smem address: [m][k] fp16, 512B rows, physical 16B chunk = (k/8) ^ (m&7)
__device__ __forceinline__ uint32_t a_addr(uint32_t base, int m, int k) {
    return base + (uint32_t)(m * 512) +
           (uint32_t)(((((k >> 3) ^ (m & 7))) << 4) + ((k & 7) << 1));
}
// packed hi/lo split store (one F2FP.PACK per half2)
__device__ __forceinline__ void store_split(unsigned char* sm, int m, int n, float v0, float v1) {
    __half2 h2 = __float22half2_rn(make_float2(v0, v1));
    float2 hf = __half22float2(h2);
    __half2 l2 = __float22half2_rn(make_float2(v0 - hf.x, v1 - hf.y));
    *(__half2*)(sm + a_addr(OFF_AH, m, n)) = h2;
    *(__half2*)(sm + a_addr(OFF_AL, m, n)) = l2;
}

// ---- prep: W2/W3 fp16 hi images, [n][k] layout, 80B rows ----
__global__ void prep_kernel(const float* __restrict__ W2, const float* __restrict__ W3) {
    int idx = blockIdx.x * blockDim.x + threadIdx.x;   // 0..131071
    int l = idx >> 16, r = idx & 65535;
    int k = r >> 8, n = r & 255;
    float w = (l ? W3 : W2)[k * 256 + n];
    __half h = __float2half_rn(w);
    int kc = k >> 5, kk = k & 31;
    *(__half*)&g_W[l][kc][n * 80 + kk * 2] = h;
}

__device__ __forceinline__ void issue_load(uint32_t smb, int g) {
    const int lc = g & 15;                    // 16 chunks per tile (8 per layer x 2 layers)
    const int l = lc >> 3, kc = lc & 7, s = g & 1;
    const uint32_t mb = smb + MB_F(s);
    MBAR_EXPECT_TX(mb, 20480);
    bulk_ld(smb + OFF_STAGE(s), &g_W[l][kc][0], 20480, mb);
}

// one 256->256 layer for 128 pixels: warp tile 64x64, 2-term split HMMA (A·Wh)
__device__ __forceinline__ void run_layer(
    float (&d)[4][8][4], uint32_t smb, int m0, int n0,
    int lane, int tid, int& g, int total_chunks)
{
    const int aRow = (lane & 7) + ((lane >> 3) & 1) * 8;   // ldmatrix A row-in-tile
    const int aCs  = lane >> 4;                            // A k8-chunk select
    const int wRow = ((lane >> 4) & 1) * 8 + (lane & 7);   // ldmatrix B row (n)
    const int wCs  = (lane >> 3) & 1;                      // B k8-chunk select

    for (int kc = 0; kc < 8; kc++) {
        const int s = g & 1;
        const uint32_t ph = (uint32_t)((g >> 1) & 1);
        mbar_wait(smb + MB_F(s), ph);
        const uint32_t stH = smb + OFF_STAGE(s);
#pragma unroll
        for (int ks = 0; ks < 2; ks++) {
            const int cb = kc * 4 + ks * 2 + aCs;          // A 16B-chunk index
            uint32_t ah[4][4], al[4][4];
#pragma unroll
            for (int mt = 0; mt < 4; mt++) {
                const int mA = m0 + mt * 16 + aRow;
                const uint32_t co = (uint32_t)((cb ^ (mA & 7)) << 4);
                LDSM4(ah[mt], smb + OFF_AH + (uint32_t)(mA * 512) + co);
                LDSM4(al[mt], smb + OFF_AL + (uint32_t)(mA * 512) + co);
            }
            const uint32_t wko = (uint32_t)((ks * 2 + wCs) << 4);
#pragma unroll
            for (int np = 0; np < 4; np++) {
                const uint32_t wro = (uint32_t)((n0 + np * 16 + wRow) * 80) + wko;
                uint32_t wh[4];
                LDSM4(wh, stH + wro);
#pragma unroll
                for (int mt = 0; mt < 4; mt++) {
                    MMA4(d[mt][np*2],   ah[mt], wh[0], wh[1]);
                    MMA4(d[mt][np*2],   al[mt], wh[0], wh[1]);
                    MMA4(d[mt][np*2+1], ah[mt], wh[2], wh[3]);
                    MMA4(d[mt][np*2+1], al[mt], wh[2], wh[3]);
                }
            }
        }
        if (lane == 0) MBAR_ARRIVE(smb + MB_U(s));         // per-warp arrive (count 8)
        if (tid == 0 && g + 2 < total_chunks) {
            mbar_wait(smb + MB_U(s), ph);                  // stage fully consumed
            issue_load(smb, g + 2);
        }
        g++;
    }
}

// layer-2 epilogue: bias+relu, packed split back to A smem
__device__ __forceinline__ void epi_store(
    unsigned char* sm, float (&d)[4][8][4], const float* bias,
    int m0, int n0, int qm, int qn)
{
#pragma unroll
    for (int mt = 0; mt < 4; mt++) {
        const int mA = m0 + mt * 16 + qm;
#pragma unroll
        for (int nt = 0; nt < 8; nt++) {
            const int n = n0 + nt * 8 + qn;
            const float bb0 = bias[n], bb1 = bias[n + 1];
            store_split(sm, mA,     n, fmaxf(d[mt][nt][0] + bb0, 0.f), fmaxf(d[mt][nt][1] + bb1, 0.f));
            store_split(sm, mA + 8, n, fmaxf(d[mt][nt][2] + bb0, 0.f), fmaxf(d[mt][nt][3] + bb1, 0.f));
        }
    }
}

// layer-3 epilogue fused with layer-4: relu(d+b3) dotted with W4 straight from
// fragments; shfl-reduce over the 4 qn-lanes; partial per n0-group into smem.
__device__ __forceinline__ void epi3_fuse(
    float (&d)[4][8][4], const float* b3v, const float* w4s, float* part,
    int m0, int n0, int wid, int lane, int qm, int qn)
{
    const int n0g = wid >> 1;
#pragma unroll
    for (int mt = 0; mt < 4; mt++) {
        float oo[2][3];
#pragma unroll
        for (int h = 0; h < 2; h++)
#pragma unroll
            for (int j = 0; j < 3; j++) oo[h][j] = 0.f;
#pragma unroll
        for (int nt = 0; nt < 8; nt++) {
            const int n = n0 + nt * 8 + qn;
            const float2 bb = *(const float2*)&b3v[n];
            const float2 wA = *(const float2*)&w4s[n * 3];
            const float2 wB = *(const float2*)&w4s[n * 3 + 2];
            const float2 wC = *(const float2*)&w4s[n * 3 + 4];
            float v0 = fmaxf(d[mt][nt][0] + bb.x, 0.f);
            float v1 = fmaxf(d[mt][nt][1] + bb.y, 0.f);
            float v2 = fmaxf(d[mt][nt][2] + bb.x, 0.f);
            float v3 = fmaxf(d[mt][nt][3] + bb.y, 0.f);
            oo[0][0] = fmaf(v0, wA.x, fmaf(v1, wB.y, oo[0][0]));
            oo[0][1] = fmaf(v0, wA.y, fmaf(v1, wC.x, oo[0][1]));
            oo[0][2] = fmaf(v0, wB.x, fmaf(v1, wC.y, oo[0][2]));
            oo[1][0] = fmaf(v2, wA.x, fmaf(v3, wB.y, oo[1][0]));
            oo[1][1] = fmaf(v2, wA.y, fmaf(v3, wC.x, oo[1][1]));
            oo[1][2] = fmaf(v2, wB.x, fmaf(v3, wC.y, oo[1][2]));
        }
#pragma unroll
        for (int h = 0; h < 2; h++)
#pragma unroll
            for (int j = 0; j < 3; j++) {
                float v = oo[h][j];
                v += __shfl_xor_sync(0xFFFFFFFFu, v, 1);
                v += __shfl_xor_sync(0xFFFFFFFFu, v, 2);
                oo[h][j] = v;
            }
        if ((lane & 3) == 0) {
#pragma unroll
            for (int h = 0; h < 2; h++) {
                const int row = m0 + mt * 16 + h * 8 + qm;
#pragma unroll
                for (int j = 0; j < 3; j++)
                    part[n0g * 384 + row * 3 + j] = oo[h][j];
            }
        }
    }
}

__global__ void __launch_bounds__(NTHR, 1) inr_hmma_kernel(
    const float* __restrict__ x, const int* __restrict__ sample_idx,
    const float* __restrict__ shiftv, const float* __restrict__ rotang,
    const float* __restrict__ cscal, const float* __restrict__ cshft,
    const float* __restrict__ W1, const float* __restrict__ b1,
    const float* __restrict__ b2, const float* __restrict__ b3,
    const float* __restrict__ W4, const float* __restrict__ b4,
    float* __restrict__ out)
{
    extern __shared__ __align__(128) unsigned char sm[];
    const uint32_t smb = smem_u32(sm);

    const int tid = threadIdx.x;
    const int lane = tid & 31, wid = tid >> 5;
    const int m0 = (wid & 1) * 64, n0 = (wid >> 1) * 64;    // warp tile 64x64
    const int qm = lane >> 2, qn = (lane & 3) * 2;

    float* w1a = (float*)(sm + OFF_W1A);
    float* w1b = (float*)(sm + OFF_W1B);
    float* b1v = (float*)(sm + OFF_B1);
    float* b2v = (float*)(sm + OFF_B2);
    float* b3v = (float*)(sm + OFF_B3);
    float* w4s = (float*)(sm + OFF_W4);
    float* part = (float*)(sm + OFF_PART);

    w1a[tid] = W1[tid]; w1b[tid] = W1[256 + tid];
    b1v[tid] = b1[tid]; b2v[tid] = b2[tid]; b3v[tid] = b3[tid];
    w4s[tid] = W4[tid]; w4s[tid + 256] = W4[tid + 256]; w4s[tid + 512] = W4[tid + 512];
    if (tid == 0) {
        MBAR_INIT(smb + MB_F(0), 1); MBAR_INIT(smb + MB_F(1), 1);
        MBAR_INIT(smb + MB_U(0), 8); MBAR_INIT(smb + MB_U(1), 8);
    }
    __syncthreads();

    const int bid = blockIdx.x, grid = gridDim.x;
    const int ntiles = (NTILES - 1 - bid) / grid + 1;
    const int total_chunks = ntiles * 16;
    int g = 0;
    if (tid == 0) { issue_load(smb, 0); issue_load(smb, 1); }

    const float2* x2 = (const float2*)x;

    for (int t = bid; t < NTILES; t += grid) {
        const int b = t >> 7;                 // 128 tiles per batch
        const int p0 = t * 128;
        const int sidx = sample_idx[b];
        const float dyv = shiftv[sidx * 2], dxv = shiftv[sidx * 2 + 1];
        float sv, cvv;
        sincosf(rotang[sidx], &sv, &cvv);

        // ---- layer 1 (SIMT) -> A hi/lo smem: 2 threads per pixel, 128 n each ----
        {
            const int px = tid >> 1, q = tid & 1;
            float2 xv = x2[p0 + px];
            const float c0 = cvv * xv.x - sv * xv.y + dxv;
            const float c1 = sv * xv.x + cvv * xv.y + dyv;
#pragma unroll
            for (int i = 0; i < 64; i++) {
                const int n = q * 128 + i * 2;
                float h0 = fmaxf(fmaf(c0, w1a[n],     fmaf(c1, w1b[n],     b1v[n])),     0.f);
                float h1 = fmaxf(fmaf(c0, w1a[n + 1], fmaf(c1, w1b[n + 1], b1v[n + 1])), 0.f);
                store_split(sm, px, n, h0, h1);
            }
            if (tid == 255 && (t & 127) == 0) {
                out[OUT_PIX + b] = dxv;
                out[OUT_PIX + 16 + b] = dyv;
            }
        }
        __syncthreads();

        float d[4][8][4];
#pragma unroll
        for (int i = 0; i < 4; i++)
#pragma unroll
            for (int j = 0; j < 8; j++)
#pragma unroll
                for (int kq = 0; kq < 4; kq++) d[i][j][kq] = 0.f;
        run_layer(d, smb, m0, n0, lane, tid, g, total_chunks);   // layer 2
        __syncthreads();
        epi_store(sm, d, b2v, m0, n0, qm, qn);
        __syncthreads();

#pragma unroll
        for (int i = 0; i < 4; i++)
#pragma unroll
            for (int j = 0; j < 8; j++)
#pragma unroll
                for (int kq = 0; kq < 4; kq++) d[i][j][kq] = 0.f;
        run_layer(d, smb, m0, n0, lane, tid, g, total_chunks);   // layer 3
        epi3_fuse(d, b3v, w4s, part, m0, n0, wid, lane, qm, qn); // fused layer 4 partials
        __syncthreads();

        // ---- final reduce: 4 n0-group partials + bias + color affine ----
        for (int it = tid; it < 384; it += NTHR) {
            const int px = it / 3, j = it - 3 * px;
            float o = part[px * 3 + j] + part[384 + px * 3 + j] +
                      part[768 + px * 3 + j] + part[1152 + px * 3 + j] + b4[j];
            if (sidx != 0)
                o = fmaf(o, cscal[sidx * 3 + j], cshft[sidx * 3 + j]);
            out[(p0 + px) * 3 + j] = o;
        }
    }
}

extern "C" void kernel_launch(void* const* d_in, const int* in_sizes, int n_in,
                              void* d_out, int out_size)
{
    (void)in_sizes; (void)n_in; (void)out_size;
    const float* x      = (const float*)d_in[0];
    const int*   sidx   = (const int*)  d_in[1];
    const float* shiftv = (const float*)d_in[2];
    const float* rotang = (const float*)d_in[3];
    const float* cscal  = (const float*)d_in[4];
    const float* cshft  = (const float*)d_in[5];
    const float* W1 = (const float*)d_in[6];
    const float* b1 = (const float*)d_in[7];
    const float* W2 = (const float*)d_in[8];
    const float* b2 = (const float*)d_in[9];
    const float* W3 = (const float*)d_in[10];
    const float* b3 = (const float*)d_in[11];
    const float* W4 = (const float*)d_in[12];
    const float* b4 = (const float*)d_in[13];
    float* out = (float*)d_out;

    int nsm = 0;
    cudaDeviceGetAttribute(&nsm, cudaDevAttrMultiProcessorCount, 0);
    if (nsm <= 0) nsm = 148;
    if (nsm > NTILES) nsm = NTILES;

    prep_kernel<<<512, 256>>>(W2, W3);

    cudaFuncSetAttribute(inr_hmma_kernel,
                         cudaFuncAttributeMaxDynamicSharedMemorySize, SMEM_ALLOC);
    inr_hmma_kernel<<<nsm, NTHR, SMEM_ALLOC>>>(
        x, sidx, shiftv, rotang, cscal, cshft, W1, b1, b2, b3, W4, b4, out);
}

// round 8
// speedup vs baseline: 7.9112x; 1.6637x over previous
#include <cuda_runtime.h>
#include <cuda_fp16.h>
#include <cstdint>
#include <math.h>

#define NTHR 256
#define NTILES 2048                  // 128 pixels per tile
#define OUT_PIX (16*128*128*3)

// ---- smem byte offsets ----
#define OFF_STAGE(s) ((s)*20480)     // 2 stages: W hi only, 20480 each
#define OFF_A   40960                // A: [128 m][256 k] fp16, 512B rows, XOR-swizzled 16B chunks
#define OFF_W1A 106496
#define OFF_W1B 107520
#define OFF_B1  108544
#define OFF_B2  109568
#define OFF_B3  110592
#define OFF_W4  111616               // float[768]
#define OFF_PART 114688              // float[4][128][3] layer-4 partials (6144 B)
#define OFF_MB  120832               // F0,F1,U0,U1
#define MB_F(s) (OFF_MB + (s)*8)
#define MB_U(s) (OFF_MB + 16 + (s)*8)
#define SMEM_ALLOC 120960

// fp16 weight images: [layer][kchunk(8 x k32)][256 n x 80B rows]
__device__ __align__(16) unsigned char g_W[2][8][20480];

// ---- helpers ----
__device__ __forceinline__ uint32_t smem_u32(const void* p) {
    uint32_t a;
    asm("{ .reg .u64 t; cvta.to.shared.u64 t, %1; cvt.u32.u64 %0, t; }" : "=r"(a) : "l"(p));
    return a;
}
#define MBAR_INIT(mbar, cnt) \
    asm volatile("mbarrier.init.shared.b64 [%0], %1;" :: "r"((uint32_t)(mbar)), "r"((uint32_t)(cnt)) : "memory")
#define MBAR_EXPECT_TX(mbar, tx) \
    asm volatile("mbarrier.arrive.expect_tx.shared.b64 _, [%0], %1;" :: "r"((uint32_t)(mbar)), "r"((uint32_t)(tx)) : "memory")
#define MBAR_ARRIVE(mbar) \
    asm volatile("mbarrier.arrive.shared.b64 _, [%0];" :: "r"((uint32_t)(mbar)) : "memory")

__device__ __forceinline__ void mbar_wait(uint32_t mbar, uint32_t parity) {
    uint32_t done;
    asm volatile("{\n\t.reg .pred p;\n\t"
                 "mbarrier.try_wait.parity.acquire.cta.shared::cta.b64 p, [%1], %2;\n\t"
                 "selp.b32 %0, 1, 0, p;\n\t}" : "=r"(done) : "r"(mbar), "r"(parity) : "memory");
    if (!done) {
        asm volatile("{\n\t.reg .pred P1;\n\t"
                     "W_%=:\n\t"
                     "mbarrier.try_wait.parity.acquire.cta.shared::cta.b64 P1, [%0], %1, 0x989680;\n\t"
                     "@P1 bra.uni D_%=;\n\t"
                     "bra.uni W_%=;\n\t"
                     "D_%=:\n\t}" :: "r"(mbar), "r"(parity) : "memory");
    }
}
__device__ __forceinline__ void bulk_ld(uint32_t dst, const void* src, uint32_t bytes, uint32_t mbar) {
    asm volatile("cp.async.bulk.shared::cluster.global.mbarrier::complete_tx::bytes [%0], [%1], %2, [%3];"
                 :: "r"(dst), "l"(src), "r"(bytes), "r"(mbar) : "memory");
}
#define LDSM4(r, addr) \
    asm volatile("ldmatrix.sync.aligned.m8n8.x4.shared.b16 {%0,%1,%2,%3}, [%4];" \
        : "=r"((r)[0]), "=r"((r)[1]), "=r"((r)[2]), "=r"((r)[3]) : "r"(addr))
#define MMA4(dd, a, b0_, b1_) \
    asm volatile("mma.sync.aligned.m16n8k16.row.col.f32.f16.f16.f32 " \
        "{%0,%1,%2,%3}, {%4,%5,%6,%7}, {%8,%9}, {%0,%1,%2,%3};" \
        : "+f"((dd)[0]), "+f"((dd)[1]), "+f"((dd)[2]), "+f"((dd)[3]) \
        : "r"((a)[0]), "r"((a)[1]), "r"((a)[2]), "r"((a)[3]), "r"(b0_), "r"(b1_))

// A smem address: [m][k] fp16, 512B rows, physical 16B chunk = (k/8) ^ (m&7)
__device__ __forceinline__ uint32_t a_addr(uint32_t base, int m, int k) {
    return base + (uint32_t)(m * 512) +
           (uint32_t)(((((k >> 3) ^ (m & 7))) << 4) + ((k & 7) << 1));
}
__device__ __forceinline__ void store_h2(unsigned char* sm, int m, int n, float v0, float v1) {
    *(__half2*)(sm + a_addr(OFF_A, m, n)) = __float22half2_rn(make_float2(v0, v1));
}

// ---- prep: W2/W3 fp16 images, [n][k] layout, 80B rows ----
__global__ void prep_kernel(const float* __restrict__ W2, const float* __restrict__ W3) {
    int idx = blockIdx.x * blockDim.x + threadIdx.x;   // 0..131071
    int l = idx >> 16, r = idx & 65535;
    int k = r >> 8, n = r & 255;
    float w = (l ? W3 : W2)[k * 256 + n];
    __half h = __float2half_rn(w);
    int kc = k >> 5, kk = k & 31;
    *(__half*)&g_W[l][kc][n * 80 + kk * 2] = h;
}

__device__ __forceinline__ void issue_load(uint32_t smb, int g) {
    const int lc = g & 15;                    // 16 chunks per tile (8 per layer x 2 layers)
    const int l = lc >> 3, kc = lc & 7, s = g & 1;
    const uint32_t mb = smb + MB_F(s);
    MBAR_EXPECT_TX(mb, 20480);
    bulk_ld(smb + OFF_STAGE(s), &g_W[l][kc][0], 20480, mb);
}

// one 256->256 layer for 128 pixels: warp tile 64x64, pure fp16 HMMA
__device__ __forceinline__ void run_layer(
    float (&d)[4][8][4], uint32_t smb, int m0, int n0,
    int lane, int tid, int& g, int total_chunks)
{
    const int aRow = (lane & 7) + ((lane >> 3) & 1) * 8;   // ldmatrix A row-in-tile
    const int aCs  = lane >> 4;                            // A k8-chunk select
    const int wRow = ((lane >> 4) & 1) * 8 + (lane & 7);   // ldmatrix B row (n)
    const int wCs  = (lane >> 3) & 1;                      // B k8-chunk select

    for (int kc = 0; kc < 8; kc++) {
        const int s = g & 1;
        const uint32_t ph = (uint32_t)((g >> 1) & 1);
        mbar_wait(smb + MB_F(s), ph);
        const uint32_t stH = smb + OFF_STAGE(s);
#pragma unroll
        for (int ks = 0; ks < 2; ks++) {
            const int cb = kc * 4 + ks * 2 + aCs;          // A 16B-chunk index
            uint32_t ah[4][4];
#pragma unroll
            for (int mt = 0; mt < 4; mt++) {
                const int mA = m0 + mt * 16 + aRow;
                const uint32_t co = (uint32_t)((cb ^ (mA & 7)) << 4);
                LDSM4(ah[mt], smb + OFF_A + (uint32_t)(mA * 512) + co);
            }
            const uint32_t wko = (uint32_t)((ks * 2 + wCs) << 4);
#pragma unroll
            for (int np = 0; np < 4; np++) {
                const uint32_t wro = (uint32_t)((n0 + np * 16 + wRow) * 80) + wko;
                uint32_t wh[4];
                LDSM4(wh, stH + wro);
#pragma unroll
                for (int mt = 0; mt < 4; mt++) {
                    MMA4(d[mt][np*2],   ah[mt], wh[0], wh[1]);
                    MMA4(d[mt][np*2+1], ah[mt], wh[2], wh[3]);
                }
            }
        }
        if (lane == 0) MBAR_ARRIVE(smb + MB_U(s));         // per-warp arrive (count 8)
        if (tid == 0 && g + 2 < total_chunks) {
            mbar_wait(smb + MB_U(s), ph);                  // stage fully consumed
            issue_load(smb, g + 2);
        }
        g++;
    }
}

// layer-2 epilogue: bias+relu, fp16 store back to A smem
__device__ __forceinline__ void epi_store(
    unsigned char* sm, float (&d)[4][8][4], const float* bias,
    int m0, int n0, int qm, int qn)
{
#pragma unroll
    for (int mt = 0; mt < 4; mt++) {
        const int mA = m0 + mt * 16 + qm;
#pragma unroll
        for (int nt = 0; nt < 8; nt++) {
            const int n = n0 + nt * 8 + qn;
            const float bb0 = bias[n], bb1 = bias[n + 1];
            store_h2(sm, mA,     n, fmaxf(d[mt][nt][0] + bb0, 0.f), fmaxf(d[mt][nt][1] + bb1, 0.f));
            store_h2(sm, mA + 8, n, fmaxf(d[mt][nt][2] + bb0, 0.f), fmaxf(d[mt][nt][3] + bb1, 0.f));
        }
    }
}

// layer-3 epilogue fused with layer-4 from fragments (fp32, unquantized)
__device__ __forceinline__ void epi3_fuse(
    float (&d)[4][8][4], const float* b3v, const float* w4s, float* part,
    int m0, int n0, int wid, int lane, int qm, int qn)
{
    const int n0g = wid >> 1;
#pragma unroll
    for (int mt = 0; mt < 4; mt++) {
        float oo[2][3];
#pragma unroll
        for (int h = 0; h < 2; h++)
#pragma unroll
            for (int j = 0; j < 3; j++) oo[h][j] = 0.f;
#pragma unroll
        for (int nt = 0; nt < 8; nt++) {
            const int n = n0 + nt * 8 + qn;
            const float2 bb = *(const float2*)&b3v[n];
            const float2 wA = *(const float2*)&w4s[n * 3];
            const float2 wB = *(const float2*)&w4s[n * 3 + 2];
            const float2 wC = *(const float2*)&w4s[n * 3 + 4];
            float v0 = fmaxf(d[mt][nt][0] + bb.x, 0.f);
            float v1 = fmaxf(d[mt][nt][1] + bb.y, 0.f);
            float v2 = fmaxf(d[mt][nt][2] + bb.x, 0.f);
            float v3 = fmaxf(d[mt][nt][3] + bb.y, 0.f);
            oo[0][0] = fmaf(v0, wA.x, fmaf(v1, wB.y, oo[0][0]));
            oo[0][1] = fmaf(v0, wA.y, fmaf(v1, wC.x, oo[0][1]));
            oo[0][2] = fmaf(v0, wB.x, fmaf(v1, wC.y, oo[0][2]));
            oo[1][0] = fmaf(v2, wA.x, fmaf(v3, wB.y, oo[1][0]));
            oo[1][1] = fmaf(v2, wA.y, fmaf(v3, wC.x, oo[1][1]));
            oo[1][2] = fmaf(v2, wB.x, fmaf(v3, wC.y, oo[1][2]));
        }
#pragma unroll
        for (int h = 0; h < 2; h++)
#pragma unroll
            for (int j = 0; j < 3; j++) {
                float v = oo[h][j];
                v += __shfl_xor_sync(0xFFFFFFFFu, v, 1);
                v += __shfl_xor_sync(0xFFFFFFFFu, v, 2);
                oo[h][j] = v;
            }
        if ((lane & 3) == 0) {
#pragma unroll
            for (int h = 0; h < 2; h++) {
                const int row = m0 + mt * 16 + h * 8 + qm;
#pragma unroll
                for (int j = 0; j < 3; j++)
                    part[n0g * 384 + row * 3 + j] = oo[h][j];
            }
        }
    }
}

__global__ void __launch_bounds__(NTHR, 1) inr_hmma_kernel(
    const float* __restrict__ x, const int* __restrict__ sample_idx,
    const float* __restrict__ shiftv, const float* __restrict__ rotang,
    const float* __restrict__ cscal, const float* __restrict__ cshft,
    const float* __restrict__ W1, const float* __restrict__ b1,
    const float* __restrict__ b2, const float* __restrict__ b3,
    const float* __restrict__ W4, const float* __restrict__ b4,
    float* __restrict__ out)
{
    extern __shared__ __align__(128) unsigned char sm[];
    const uint32_t smb = smem_u32(sm);

    const int tid = threadIdx.x;
    const int lane = tid & 31, wid = tid >> 5;
    const int m0 = (wid & 1) * 64, n0 = (wid >> 1) * 64;    // warp tile 64x64
    const int qm = lane >> 2, qn = (lane & 3) * 2;

    float* w1a = (float*)(sm + OFF_W1A);
    float* w1b = (float*)(sm + OFF_W1B);
    float* b1v = (float*)(sm + OFF_B1);
    float* b2v = (float*)(sm + OFF_B2);
    float* b3v = (float*)(sm + OFF_B3);
    float* w4s = (float*)(sm + OFF_W4);
    float* part = (float*)(sm + OFF_PART);

    w1a[tid] = W1[tid]; w1b[tid] = W1[256 + tid];
    b1v[tid] = b1[tid]; b2v[tid] = b2[tid]; b3v[tid] = b3[tid];
    w4s[tid] = W4[tid]; w4s[tid + 256] = W4[tid + 256]; w4s[tid + 512] = W4[tid + 512];
    if (tid == 0) {
        MBAR_INIT(smb + MB_F(0), 1); MBAR_INIT(smb + MB_F(1), 1);
        MBAR_INIT(smb + MB_U(0), 8); MBAR_INIT(smb + MB_U(1), 8);
    }
    __syncthreads();

    const int bid = blockIdx.x, grid = gridDim.x;
    const int ntiles = (NTILES - 1 - bid) / grid + 1;
    const int total_chunks = ntiles * 16;
    int g = 0;
    if (tid == 0) { issue_load(smb, 0); issue_load(smb, 1); }

    const float2* x2 = (const float2*)x;

    for (int t = bid; t < NTILES; t += grid) {
        const int b = t >> 7;                 // 128 tiles per batch
        const int p0 = t * 128;
        const int sidx = sample_idx[b];
        const float dyv = shiftv[sidx * 2], dxv = shiftv[sidx * 2 + 1];
        float sv, cvv;
        sincosf(rotang[sidx], &sv, &cvv);

        // ---- layer 1 (SIMT) -> A fp16 smem: 2 threads per pixel, 128 n each ----
        {
            const int px = tid >> 1, q = tid & 1;
            float2 xv = x2[p0 + px];
            const float c0 = cvv * xv.x - sv * xv.y + dxv;
            const float c1 = sv * xv.x + cvv * xv.y + dyv;
#pragma unroll
            for (int i = 0; i < 64; i++) {
                const int n = q * 128 + i * 2;
                float h0 = fmaxf(fmaf(c0, w1a[n],     fmaf(c1, w1b[n],     b1v[n])),     0.f);
                float h1 = fmaxf(fmaf(c0, w1a[n + 1], fmaf(c1, w1b[n + 1], b1v[n + 1])), 0.f);
                store_h2(sm, px, n, h0, h1);
            }
            if (tid == 255 && (t & 127) == 0) {
                out[OUT_PIX + b] = dxv;
                out[OUT_PIX + 16 + b] = dyv;
            }
        }
        __syncthreads();

        float d[4][8][4];
#pragma unroll
        for (int i = 0; i < 4; i++)
#pragma unroll
            for (int j = 0; j < 8; j++)
#pragma unroll
                for (int kq = 0; kq < 4; kq++) d[i][j][kq] = 0.f;
        run_layer(d, smb, m0, n0, lane, tid, g, total_chunks);   // layer 2
        __syncthreads();
        epi_store(sm, d, b2v, m0, n0, qm, qn);
        __syncthreads();

#pragma unroll
        for (int i = 0; i < 4; i++)
#pragma unroll
            for (int j = 0; j < 8; j++)
#pragma unroll
                for (int kq = 0; kq < 4; kq++) d[i][j][kq] = 0.f;
        run_layer(d, smb, m0, n0, lane, tid, g, total_chunks);   // layer 3
        epi3_fuse(d, b3v, w4s, part, m0, n0, wid, lane, qm, qn); // fused layer 4 partials
        __syncthreads();

        // ---- final reduce: 4 n0-group partials + bias + color affine ----
        for (int it = tid; it < 384; it += NTHR) {
            const int px = it / 3, j = it - 3 * px;
            float o = part[px * 3 + j] + part[384 + px * 3 + j] +
                      part[768 + px * 3 + j] + part[1152 + px * 3 + j] + b4[j];
            if (sidx != 0)
                o = fmaf(o, cscal[sidx * 3 + j], cshft[sidx * 3 + j]);
            out[(p0 + px) * 3 + j] = o;
        }
    }
}

extern "C" void kernel_launch(void* const* d_in, const int* in_sizes, int n_in,
                              void* d_out, int out_size)
{
    (void)in_sizes; (void)n_in; (void)out_size;
    const float* x      = (const float*)d_in[0];
    const int*   sidx   = (const int*)  d_in[1];
    const float* shiftv = (const float*)d_in[2];
    const float* rotang = (const float*)d_in[3];
    const float* cscal  = (const float*)d_in[4];
    const float* cshft  = (const float*)d_in[5];
    const float* W1 = (const float*)d_in[6];
    const float* b1 = (const float*)d_in[7];
    const float* W2 = (const float*)d_in[8];
    const float* b2 = (const float*)d_in[9];
    const float* W3 = (const float*)d_in[10];
    const float* b3 = (const float*)d_in[11];
    const float* W4 = (const float*)d_in[12];
    const float* b4 = (const float*)d_in[13];
    float* out = (float*)d_out;

    int nsm = 0;
    cudaDeviceGetAttribute(&nsm, cudaDevAttrMultiProcessorCount, 0);
    if (nsm <= 0) nsm = 148;
    if (nsm > NTILES) nsm = NTILES;

    prep_kernel<<<512, 256>>>(W2, W3);

    cudaFuncSetAttribute(inr_hmma_kernel,
                         cudaFuncAttributeMaxDynamicSharedMemorySize, SMEM_ALLOC);
    inr_hmma_kernel<<<nsm, NTHR, SMEM_ALLOC>>>(
        x, sidx, shiftv, rotang, cscal, cshft, W1, b1, b2, b3, W4, b4, out);
}